// round 2
// baseline (speedup 1.0000x reference)
#include <cuda_runtime.h>
#include <cuda_bf16.h>
#include <cstdint>
#include <cstddef>

// Problem constants
#define DIMN 256
#define KTOK 2048
#define BSZ  256

// ---------------- device globals (scratch; no allocs allowed) ----------------
__device__ __align__(16) float          g_qq[BSZ * DIMN];   // query@Wq^T + bq + bref
__device__ __align__(16) __nv_bfloat16  g_Wh[DIMN * DIMN];  // Wref hi split
__device__ __align__(16) __nv_bfloat16  g_Wl[DIMN * DIMN];  // Wref lo split

// ---------------- helpers ----------------
__device__ __forceinline__ uint32_t smem_u32(const void* p) {
    return (uint32_t)__cvta_generic_to_shared(p);
}

__device__ __forceinline__ uint32_t swz(uint32_t o) {
    return o ^ ((o >> 3) & 0x70);
}

__device__ __forceinline__ uint32_t pack2(__nv_bfloat16 a, __nv_bfloat16 b) {
    __nv_bfloat162 t(a, b);  // a at low half
    return *reinterpret_cast<uint32_t*>(&t);
}

__device__ __forceinline__ void split_bf16(float a, __nv_bfloat16& h, __nv_bfloat16& l) {
    h = __float2bfloat16(a);
    l = __float2bfloat16(a - __bfloat162float(h));
}

__device__ __forceinline__ float tanha(float x) {
    float y;
    asm("tanh.approx.f32 %0, %1;" : "=f"(y) : "f"(x));
    return y;
}

__device__ __forceinline__ void ldsm4(uint32_t* r, uint32_t addr) {
    asm volatile("ldmatrix.sync.aligned.m8n8.x4.shared.b16 {%0,%1,%2,%3}, [%4];"
                 : "=r"(r[0]), "=r"(r[1]), "=r"(r[2]), "=r"(r[3])
                 : "r"(addr));
}

__device__ __forceinline__ void mma_bf16(float* c, const uint32_t* a,
                                         uint32_t b0, uint32_t b1) {
    asm volatile(
        "mma.sync.aligned.m16n8k16.row.col.f32.bf16.bf16.f32 "
        "{%0,%1,%2,%3}, {%4,%5,%6,%7}, {%8,%9}, {%0,%1,%2,%3};"
        : "+f"(c[0]), "+f"(c[1]), "+f"(c[2]), "+f"(c[3])
        : "r"(a[0]), "r"(a[1]), "r"(a[2]), "r"(a[3]), "r"(b0), "r"(b1));
}

__device__ __forceinline__ void cp_async16(uint32_t dst, const void* src) {
    asm volatile("cp.async.cg.shared.global [%0], [%1], 16;"
                 :: "r"(dst), "l"(src) : "memory");
}

// ---------------- prep kernels ----------------
// qq[b,d] = sum_e query[b,e]*Wq[d,e] + bq[d] + bref[d]
__global__ void prep_qq(const float* __restrict__ query, const float* __restrict__ Wq,
                        const float* __restrict__ bq, const float* __restrict__ bref) {
    __shared__ float qrow[DIMN];
    int b = blockIdx.x, d = threadIdx.x;
    qrow[d] = query[b * DIMN + d];
    __syncthreads();
    const float* w = Wq + d * DIMN;
    float s = bq[d] + bref[d];
#pragma unroll 8
    for (int e = 0; e < DIMN; e++) s = fmaf(qrow[e], w[e], s);
    g_qq[b * DIMN + d] = s;
}

__global__ void prep_split(const float* __restrict__ Wref) {
    int i = blockIdx.x * blockDim.x + threadIdx.x;  // 65536 total
    float w = Wref[i];
    __nv_bfloat16 h, l;
    split_bf16(w, h, l);
    g_Wh[i] = h;
    g_Wl[i] = l;
}

// ---------------- main kernel ----------------
// SMEM layout (dynamic, offsets from base):
//   [0]      A_hi  128 rows x 128B (K-chunk = 64 bf16), SW128   (16384)
//   [16384]  A_lo                                               (16384)
//   [32768]  W_hi  256 rows x 128B                              (32768)
//   [65536]  W_lo                                               (32768)
//   [98304]  v     256 floats                                   (1024)
#define SM_AHI 0
#define SM_ALO 16384
#define SM_WHI 32768
#define SM_WLO 65536
#define SM_V   98304
#define SMEM_TOTAL 99328

__global__ void __launch_bounds__(256, 1) attn_main(const float* __restrict__ enc,
                                                    const float* __restrict__ vvec,
                                                    float* __restrict__ out) {
    extern __shared__ char smem[];
    const uint32_t sb = smem_u32(smem);
    const int tid = threadIdx.x;
    const int wid = tid >> 5;
    const int lane = tid & 31;
    const int k = blockIdx.x;
    const int b0 = blockIdx.y * 128;
    const int kb = k * BSZ + b0;       // global row base of this CTA's A tile
    const int m0 = wid * 16;           // warp's row base within the tile

    float* v_s = (float*)(smem + SM_V);
    v_s[tid] = vvec[tid];
    __syncthreads();

    // fp32 accumulators: 32 n-tiles x 4 regs (rows lane/4, lane/4+8; cols 2*(lane%4)+{0,1})
    float acc[32][4];
#pragma unroll
    for (int t = 0; t < 32; t++)
#pragma unroll
        for (int j = 0; j < 4; j++) acc[t][j] = 0.0f;

    // per-lane ldmatrix base offsets
    // A: lanes 0-15 -> rows m0+(l&15) @ k-low16; lanes 16-31 -> same rows @ k-high16
    const uint32_t a_off0 = (uint32_t)((m0 + (lane & 15)) * 128 + (lane >> 4) * 16);
    // W: lanes 0-7: d n0..n0+7 k-low; 8-15: same d k-high; 16-23: d+8 k-low; 24-31: d+8 k-high
    const uint32_t w_row = (uint32_t)((lane & 7) + ((lane & 16) ? 8 : 0));
    const uint32_t w_off0 = w_row * 128 + ((lane >> 3) & 1) * 16;

    // A stage registers (one chunk = 8 float4 per thread)
    float4 st[8];
#pragma unroll
    for (int j = 0; j < 8; j++) {
        int gi = j * 256 + tid;
        int m = gi >> 4, f4 = gi & 15;
        st[j] = *(const float4*)(enc + (size_t)(kb + m) * DIMN + /*c=0*/ f4 * 4);
    }

    for (int c = 0; c < 4; c++) {
        if (c) __syncthreads();  // previous chunk's compute done reading smem

        // stream W chunk via cp.async (bf16, pre-split in global)
#pragma unroll
        for (int j = 0; j < 8; j++) {
            int gi = j * 256 + tid;           // 2048 granules of 16B
            int d = gi >> 3, seg = gi & 7;
            cp_async16(sb + SM_WHI + swz((uint32_t)(d * 128 + seg * 16)),
                       g_Wh + d * DIMN + c * 64 + seg * 8);
        }
#pragma unroll
        for (int j = 0; j < 8; j++) {
            int gi = j * 256 + tid;
            int d = gi >> 3, seg = gi & 7;
            cp_async16(sb + SM_WLO + swz((uint32_t)(d * 128 + seg * 16)),
                       g_Wl + d * DIMN + c * 64 + seg * 8);
        }
        asm volatile("cp.async.commit_group;" ::: "memory");

        // convert + store staged A chunk (hi/lo split), SW128 layout
#pragma unroll
        for (int j = 0; j < 8; j++) {
            int gi = j * 256 + tid;
            int m = gi >> 4, f4 = gi & 15;
            __nv_bfloat16 h0, h1, h2, h3, l0, l1, l2, l3;
            split_bf16(st[j].x, h0, l0);
            split_bf16(st[j].y, h1, l1);
            split_bf16(st[j].z, h2, l2);
            split_bf16(st[j].w, h3, l3);
            uint32_t sw = swz((uint32_t)(m * 128 + f4 * 8));
            *(uint2*)(smem + SM_AHI + sw) = make_uint2(pack2(h0, h1), pack2(h2, h3));
            *(uint2*)(smem + SM_ALO + sw) = make_uint2(pack2(l0, l1), pack2(l2, l3));
        }

        // prefetch next A chunk into registers (overlaps with compute below)
        if (c < 3) {
#pragma unroll
            for (int j = 0; j < 8; j++) {
                int gi = j * 256 + tid;
                int m = gi >> 4, f4 = gi & 15;
                st[j] = *(const float4*)(enc + (size_t)(kb + m) * DIMN +
                                         (c + 1) * 64 + f4 * 4);
            }
        }

        asm volatile("cp.async.wait_group 0;" ::: "memory");
        __syncthreads();

        // ---- compute this chunk: 4 k-steps x 32 n-tiles x 3 split terms ----
#pragma unroll
        for (int kk = 0; kk < 4; kk++) {
            uint32_t aH[4], aL[4];
            ldsm4(aH, sb + SM_AHI + swz(a_off0 + kk * 32));
            ldsm4(aL, sb + SM_ALO + swz(a_off0 + kk * 32));
#pragma unroll
            for (int np = 0; np < 16; np++) {
                uint32_t wh[4], wl[4];
                ldsm4(wh, sb + SM_WHI + swz(w_off0 + np * 2048 + kk * 32));
                mma_bf16(acc[2 * np],     aH, wh[0], wh[1]);
                mma_bf16(acc[2 * np + 1], aH, wh[2], wh[3]);
                mma_bf16(acc[2 * np],     aL, wh[0], wh[1]);
                mma_bf16(acc[2 * np + 1], aL, wh[2], wh[3]);
                ldsm4(wl, sb + SM_WLO + swz(w_off0 + np * 2048 + kk * 32));
                mma_bf16(acc[2 * np],     aH, wl[0], wl[1]);
                mma_bf16(acc[2 * np + 1], aH, wl[2], wl[3]);
            }
        }
    }

    // ---- epilogue: u[r] = sum_d v[d]*tanh(C[r,d] + qq[b,d]); logit = 10*tanh(u) ----
    const int q = lane >> 2;
    const int r0g = b0 + m0 + q;        // b index of fragment row 0
    const int r1g = r0g + 8;            // fragment row 1
    const float* q0p = g_qq + (size_t)r0g * DIMN;
    const float* q1p = g_qq + (size_t)r1g * DIMN;
    const int cbase = 2 * (lane & 3);

    float u0 = 0.0f, u1 = 0.0f;
#pragma unroll
    for (int t = 0; t < 32; t++) {
        int cb = t * 8 + cbase;
        float2 qa = *(const float2*)(q0p + cb);
        float2 qb = *(const float2*)(q1p + cb);
        float2 vv = *(const float2*)(v_s + cb);
        u0 = fmaf(vv.x, tanha(acc[t][0] + qa.x), u0);
        u0 = fmaf(vv.y, tanha(acc[t][1] + qa.y), u0);
        u1 = fmaf(vv.x, tanha(acc[t][2] + qb.x), u1);
        u1 = fmaf(vv.y, tanha(acc[t][3] + qb.y), u1);
    }
    // reduce across the 4 lanes (lane&3) that share each row
    u0 += __shfl_xor_sync(0xFFFFFFFF, u0, 1);
    u0 += __shfl_xor_sync(0xFFFFFFFF, u0, 2);
    u1 += __shfl_xor_sync(0xFFFFFFFF, u1, 1);
    u1 += __shfl_xor_sync(0xFFFFFFFF, u1, 2);

    if ((lane & 3) == 0) {
        out[(size_t)r0g * KTOK + k] = 10.0f * tanhf(u0);
        out[(size_t)r1g * KTOK + k] = 10.0f * tanhf(u1);
    }
}

// ---------------- launch ----------------
extern "C" void kernel_launch(void* const* d_in, const int* in_sizes, int n_in,
                              void* d_out, int out_size) {
    (void)in_sizes; (void)n_in; (void)out_size;
    const float* enc   = (const float*)d_in[0];
    const float* query = (const float*)d_in[1];
    const float* Wq    = (const float*)d_in[2];
    const float* bq    = (const float*)d_in[3];
    const float* Wref  = (const float*)d_in[4];
    const float* bref  = (const float*)d_in[5];
    const float* v     = (const float*)d_in[6];
    float* out = (float*)d_out;

    prep_qq<<<BSZ, DIMN>>>(query, Wq, bq, bref);
    prep_split<<<DIMN * DIMN / 256, 256>>>(Wref);

    cudaFuncSetAttribute(attn_main, cudaFuncAttributeMaxDynamicSharedMemorySize,
                         SMEM_TOTAL);
    dim3 grid(KTOK, 2);
    attn_main<<<grid, 256, SMEM_TOTAL>>>(enc, v, out);
}

// round 3
// speedup vs baseline: 1.1132x; 1.1132x over previous
#include <cuda_runtime.h>
#include <cuda_bf16.h>
#include <cstdint>
#include <cstddef>

// Problem constants
#define DIMN 256
#define KTOK 2048
#define BSZ  256

// ---------------- device globals (scratch; no allocs allowed) ----------------
__device__ __align__(16) float          g_qq[BSZ * DIMN];   // query@Wq^T + bq + bref
__device__ __align__(16) __nv_bfloat16  g_Wh[DIMN * DIMN];  // Wref hi split
__device__ __align__(16) __nv_bfloat16  g_Wl[DIMN * DIMN];  // Wref lo split

// ---------------- helpers ----------------
__device__ __forceinline__ uint32_t smem_u32(const void* p) {
    return (uint32_t)__cvta_generic_to_shared(p);
}

__device__ __forceinline__ uint32_t swz(uint32_t o) {
    return o ^ ((o >> 3) & 0x70);
}

__device__ __forceinline__ uint32_t pack2(__nv_bfloat16 a, __nv_bfloat16 b) {
    __nv_bfloat162 t(a, b);  // a at low half
    return *reinterpret_cast<uint32_t*>(&t);
}

__device__ __forceinline__ void split_bf16(float a, __nv_bfloat16& h, __nv_bfloat16& l) {
    h = __float2bfloat16(a);
    l = __float2bfloat16(a - __bfloat162float(h));
}

__device__ __forceinline__ float tanha(float x) {
    float y;
    asm("tanh.approx.f32 %0, %1;" : "=f"(y) : "f"(x));
    return y;
}

__device__ __forceinline__ void ldsm4(uint32_t* r, uint32_t addr) {
    asm volatile("ldmatrix.sync.aligned.m8n8.x4.shared.b16 {%0,%1,%2,%3}, [%4];"
                 : "=r"(r[0]), "=r"(r[1]), "=r"(r[2]), "=r"(r[3])
                 : "r"(addr));
}

__device__ __forceinline__ void mma_bf16(float* c, const uint32_t* a,
                                         uint32_t b0, uint32_t b1) {
    asm volatile(
        "mma.sync.aligned.m16n8k16.row.col.f32.bf16.bf16.f32 "
        "{%0,%1,%2,%3}, {%4,%5,%6,%7}, {%8,%9}, {%0,%1,%2,%3};"
        : "+f"(c[0]), "+f"(c[1]), "+f"(c[2]), "+f"(c[3])
        : "r"(a[0]), "r"(a[1]), "r"(a[2]), "r"(a[3]), "r"(b0), "r"(b1));
}

__device__ __forceinline__ void cp_async16(uint32_t dst, const void* src) {
    asm volatile("cp.async.cg.shared.global [%0], [%1], 16;"
                 :: "r"(dst), "l"(src) : "memory");
}

// ---------------- prep kernels ----------------
// qq[b,d] = sum_e query[b,e]*Wq[d,e] + bq[d] + bref[d]
// ILP version: 4 independent accumulators, float4 loads.
__global__ void prep_qq(const float* __restrict__ query, const float* __restrict__ Wq,
                        const float* __restrict__ bq, const float* __restrict__ bref) {
    __shared__ __align__(16) float qrow[DIMN];
    int b = blockIdx.x, d = threadIdx.x;
    qrow[d] = query[b * DIMN + d];
    __syncthreads();
    const float4* w = (const float4*)(Wq + (size_t)d * DIMN);
    const float4* q4 = (const float4*)qrow;
    float s0 = 0.f, s1 = 0.f, s2 = 0.f, s3 = 0.f;
#pragma unroll
    for (int e = 0; e < 64; e += 4) {
        float4 wa = w[e], wb = w[e + 1], wc = w[e + 2], wd = w[e + 3];
        float4 qa = q4[e], qb = q4[e + 1], qc = q4[e + 2], qd = q4[e + 3];
        s0 = fmaf(wa.x, qa.x, s0); s1 = fmaf(wa.y, qa.y, s1);
        s2 = fmaf(wa.z, qa.z, s2); s3 = fmaf(wa.w, qa.w, s3);
        s0 = fmaf(wb.x, qb.x, s0); s1 = fmaf(wb.y, qb.y, s1);
        s2 = fmaf(wb.z, qb.z, s2); s3 = fmaf(wb.w, qb.w, s3);
        s0 = fmaf(wc.x, qc.x, s0); s1 = fmaf(wc.y, qc.y, s1);
        s2 = fmaf(wc.z, qc.z, s2); s3 = fmaf(wc.w, qc.w, s3);
        s0 = fmaf(wd.x, qd.x, s0); s1 = fmaf(wd.y, qd.y, s1);
        s2 = fmaf(wd.z, qd.z, s2); s3 = fmaf(wd.w, qd.w, s3);
    }
    g_qq[b * DIMN + d] = (s0 + s1) + (s2 + s3) + bq[d] + bref[d];
}

__global__ void prep_split(const float* __restrict__ Wref) {
    int i = blockIdx.x * blockDim.x + threadIdx.x;  // 65536 total
    float w = Wref[i];
    __nv_bfloat16 h, l;
    split_bf16(w, h, l);
    g_Wh[i] = h;
    g_Wl[i] = l;
}

// ---------------- main kernel ----------------
// SMEM layout (dynamic, offsets from base), double-buffered:
//   A stage p (p=0,1): base = p*32768;       hi at +0, lo at +16384  (32KB/stage)
//   W stage p:         base = 65536+p*65536; hi at +0, lo at +32768  (64KB/stage)
//   v: 196608 (1KB)
#define SM_W_BASE 65536
#define SM_V      196608
#define SMEM_TOTAL 197632

__global__ void __launch_bounds__(256, 1) attn_main(const float* __restrict__ enc,
                                                    const float* __restrict__ vvec,
                                                    float* __restrict__ out) {
    extern __shared__ char smem[];
    const uint32_t sb = smem_u32(smem);
    const int tid = threadIdx.x;
    const int wid = tid >> 5;
    const int lane = tid & 31;
    const int k = blockIdx.x;
    const int b0 = blockIdx.y * 128;
    const int kb = k * BSZ + b0;       // global row base of this CTA's A tile
    const int m0 = wid * 16;           // warp's row base within the tile

    float* v_s = (float*)(smem + SM_V);
    v_s[tid] = vvec[tid];

    // fp32 accumulators: 32 n-tiles x 4 regs
    float acc[32][4];
#pragma unroll
    for (int t = 0; t < 32; t++)
#pragma unroll
        for (int j = 0; j < 4; j++) acc[t][j] = 0.0f;

    // per-lane ldmatrix base offsets (within a stage)
    const uint32_t a_off0 = (uint32_t)((m0 + (lane & 15)) * 128 + (lane >> 4) * 16);
    const uint32_t w_row = (uint32_t)((lane & 7) + ((lane & 16) ? 8 : 0));
    const uint32_t w_off0 = w_row * 128 + ((lane >> 3) & 1) * 16;

    // W-chunk cp.async issue (16 x 16B granules per thread: hi then lo)
    auto issue_W = [&](int c) {
        uint32_t wst = sb + SM_W_BASE + (uint32_t)(c & 1) * 65536;
#pragma unroll
        for (int j = 0; j < 8; j++) {
            int gi = j * 256 + tid;           // 2048 granules of 16B
            int d = gi >> 3, seg = gi & 7;
            cp_async16(wst + swz((uint32_t)(d * 128 + seg * 16)),
                       g_Wh + d * DIMN + c * 64 + seg * 8);
        }
#pragma unroll
        for (int j = 0; j < 8; j++) {
            int gi = j * 256 + tid;
            int d = gi >> 3, seg = gi & 7;
            cp_async16(wst + 32768 + swz((uint32_t)(d * 128 + seg * 16)),
                       g_Wl + d * DIMN + c * 64 + seg * 8);
        }
        asm volatile("cp.async.commit_group;" ::: "memory");
    };

    // ---- prologue: W0 in flight, A0 in regs ----
    issue_W(0);
    float4 st[8];
#pragma unroll
    for (int j = 0; j < 8; j++) {
        int gi = j * 256 + tid;
        int m = gi >> 4, f4 = gi & 15;
        st[j] = *(const float4*)(enc + (size_t)(kb + m) * DIMN + f4 * 4);
    }

    for (int c = 0; c < 4; c++) {
        const uint32_t abase = sb + (uint32_t)(c & 1) * 32768;
        const uint32_t wbase = sb + SM_W_BASE + (uint32_t)(c & 1) * 65536;

        // split + STS A chunk c into stage c&1 (disjoint from laggards' buffers)
#pragma unroll
        for (int j = 0; j < 8; j++) {
            int gi = j * 256 + tid;
            int m = gi >> 4, f4 = gi & 15;
            __nv_bfloat16 h0, h1, h2, h3, l0, l1, l2, l3;
            split_bf16(st[j].x, h0, l0);
            split_bf16(st[j].y, h1, l1);
            split_bf16(st[j].z, h2, l2);
            split_bf16(st[j].w, h3, l3);
            uint32_t sw = swz((uint32_t)(m * 128 + f4 * 8));
            char* ab = (char*)smem + (size_t)(c & 1) * 32768;
            *(uint2*)(ab + sw) = make_uint2(pack2(h0, h1), pack2(h2, h3));
            *(uint2*)(ab + 16384 + sw) = make_uint2(pack2(l0, l1), pack2(l2, l3));
        }

        // prefetch next A chunk into regs (overlaps everything below)
        if (c < 3) {
#pragma unroll
            for (int j = 0; j < 8; j++) {
                int gi = j * 256 + tid;
                int m = gi >> 4, f4 = gi & 15;
                st[j] = *(const float4*)(enc + (size_t)(kb + m) * DIMN +
                                         (c + 1) * 64 + f4 * 4);
            }
        }

        // W_c arrived (issued one full compute phase ago for c>0)
        asm volatile("cp.async.wait_group 0;" ::: "memory");
        __syncthreads();

        // issue W_{c+1} into the other stage (safe: all warps past compute c-1)
        if (c < 3) issue_W(c + 1);

        // ---- compute chunk c ----
#pragma unroll
        for (int kk = 0; kk < 4; kk++) {
            uint32_t aH[4], aL[4];
            ldsm4(aH, abase + swz(a_off0 + kk * 32));
            ldsm4(aL, abase + 16384 + swz(a_off0 + kk * 32));
#pragma unroll
            for (int np = 0; np < 16; np++) {
                uint32_t wh[4], wl[4];
                ldsm4(wh, wbase + swz(w_off0 + np * 2048 + kk * 32));
                mma_bf16(acc[2 * np],     aH, wh[0], wh[1]);
                mma_bf16(acc[2 * np + 1], aH, wh[2], wh[3]);
                mma_bf16(acc[2 * np],     aL, wh[0], wh[1]);
                mma_bf16(acc[2 * np + 1], aL, wh[2], wh[3]);
                ldsm4(wl, wbase + 32768 + swz(w_off0 + np * 2048 + kk * 32));
                mma_bf16(acc[2 * np],     aH, wl[0], wl[1]);
                mma_bf16(acc[2 * np + 1], aH, wl[2], wl[3]);
            }
        }
    }

    // ---- epilogue: u[r] = sum_d v[d]*tanh(C[r,d] + qq[b,d]); logit = 10*tanh(u) ----
    const int q = lane >> 2;
    const int r0g = b0 + m0 + q;        // b index of fragment row 0
    const int r1g = r0g + 8;            // fragment row 1
    const float* q0p = g_qq + (size_t)r0g * DIMN;
    const float* q1p = g_qq + (size_t)r1g * DIMN;
    const int cbase = 2 * (lane & 3);

    float u0 = 0.0f, u1 = 0.0f;
#pragma unroll
    for (int t = 0; t < 32; t++) {
        int cb = t * 8 + cbase;
        float2 qa = *(const float2*)(q0p + cb);
        float2 qb = *(const float2*)(q1p + cb);
        float2 vv = *(const float2*)(v_s + cb);
        u0 = fmaf(vv.x, tanha(acc[t][0] + qa.x), u0);
        u0 = fmaf(vv.y, tanha(acc[t][1] + qa.y), u0);
        u1 = fmaf(vv.x, tanha(acc[t][2] + qb.x), u1);
        u1 = fmaf(vv.y, tanha(acc[t][3] + qb.y), u1);
    }
    // reduce across the 4 lanes that share each row
    u0 += __shfl_xor_sync(0xFFFFFFFF, u0, 1);
    u0 += __shfl_xor_sync(0xFFFFFFFF, u0, 2);
    u1 += __shfl_xor_sync(0xFFFFFFFF, u1, 1);
    u1 += __shfl_xor_sync(0xFFFFFFFF, u1, 2);

    if ((lane & 3) == 0) {
        out[(size_t)r0g * KTOK + k] = 10.0f * tanhf(u0);
        out[(size_t)r1g * KTOK + k] = 10.0f * tanhf(u1);
    }
}

// ---------------- launch ----------------
extern "C" void kernel_launch(void* const* d_in, const int* in_sizes, int n_in,
                              void* d_out, int out_size) {
    (void)in_sizes; (void)n_in; (void)out_size;
    const float* enc   = (const float*)d_in[0];
    const float* query = (const float*)d_in[1];
    const float* Wq    = (const float*)d_in[2];
    const float* bq    = (const float*)d_in[3];
    const float* Wref  = (const float*)d_in[4];
    const float* bref  = (const float*)d_in[5];
    const float* v     = (const float*)d_in[6];
    float* out = (float*)d_out;

    prep_qq<<<BSZ, DIMN>>>(query, Wq, bq, bref);
    prep_split<<<DIMN * DIMN / 256, 256>>>(Wref);

    cudaFuncSetAttribute(attn_main, cudaFuncAttributeMaxDynamicSharedMemorySize,
                         SMEM_TOTAL);
    dim3 grid(KTOK, 2);
    attn_main<<<grid, 256, SMEM_TOTAL>>>(enc, v, out);
}

// round 4
// speedup vs baseline: 1.1268x; 1.0123x over previous
#include <cuda_runtime.h>
#include <cuda_bf16.h>
#include <cstdint>
#include <cstddef>

// Problem constants
#define DIMN 256
#define KTOK 2048
#define BSZ  256

// ---------------- device globals (scratch; no allocs allowed) ----------------
__device__ __align__(16) float          g_qq[BSZ * DIMN];   // query@Wq^T + bq + bref
__device__ __align__(16) __nv_bfloat16  g_Wh[DIMN * DIMN];  // Wref hi split
__device__ __align__(16) __nv_bfloat16  g_Wl[DIMN * DIMN];  // Wref lo split

// ---------------- helpers ----------------
__device__ __forceinline__ uint32_t smem_u32(const void* p) {
    return (uint32_t)__cvta_generic_to_shared(p);
}

__device__ __forceinline__ uint32_t swz(uint32_t o) {
    return o ^ ((o >> 3) & 0x70);
}

__device__ __forceinline__ uint32_t pack2(__nv_bfloat16 a, __nv_bfloat16 b) {
    __nv_bfloat162 t(a, b);  // a at low half
    return *reinterpret_cast<uint32_t*>(&t);
}

__device__ __forceinline__ void split_bf16(float a, __nv_bfloat16& h, __nv_bfloat16& l) {
    h = __float2bfloat16(a);
    l = __float2bfloat16(a - __bfloat162float(h));
}

__device__ __forceinline__ float tanha(float x) {
    float y;
    asm("tanh.approx.f32 %0, %1;" : "=f"(y) : "f"(x));
    return y;
}

__device__ __forceinline__ void ldsm4(uint32_t* r, uint32_t addr) {
    asm volatile("ldmatrix.sync.aligned.m8n8.x4.shared.b16 {%0,%1,%2,%3}, [%4];"
                 : "=r"(r[0]), "=r"(r[1]), "=r"(r[2]), "=r"(r[3])
                 : "r"(addr));
}

__device__ __forceinline__ void mma_bf16(float* c, const uint32_t* a,
                                         uint32_t b0, uint32_t b1) {
    asm volatile(
        "mma.sync.aligned.m16n8k16.row.col.f32.bf16.bf16.f32 "
        "{%0,%1,%2,%3}, {%4,%5,%6,%7}, {%8,%9}, {%0,%1,%2,%3};"
        : "+f"(c[0]), "+f"(c[1]), "+f"(c[2]), "+f"(c[3])
        : "r"(a[0]), "r"(a[1]), "r"(a[2]), "r"(a[3]), "r"(b0), "r"(b1));
}

__device__ __forceinline__ void cp_async16(uint32_t dst, const void* src) {
    asm volatile("cp.async.cg.shared.global [%0], [%1], 16;"
                 :: "r"(dst), "l"(src) : "memory");
}

// ---------------- prep kernels ----------------
// qq[b,d] = sum_e query[b,e]*Wq[d,e] + bq[d] + bref[d]
// Warp-cooperative: warp handles 32 d's, lanes cover the 256-wide row (coalesced).
__global__ void prep_qq(const float* __restrict__ query, const float* __restrict__ Wq,
                        const float* __restrict__ bq, const float* __restrict__ bref) {
    __shared__ __align__(16) float qrow[DIMN];
    const int b = blockIdx.x;
    const int tid = threadIdx.x, lane = tid & 31, w = tid >> 5;
    qrow[tid] = query[b * DIMN + tid];
    __syncthreads();
    const float4* q4 = (const float4*)qrow;
    const float4 y0 = q4[lane * 2], y1 = q4[lane * 2 + 1];
#pragma unroll 4
    for (int i = 0; i < 32; i++) {
        const int d = w * 32 + i;
        const float4* wq = (const float4*)(Wq + (size_t)d * DIMN);
        const float4 x0 = wq[lane * 2], x1 = wq[lane * 2 + 1];
        float s = x0.x * y0.x + x0.y * y0.y + x0.z * y0.z + x0.w * y0.w +
                  x1.x * y1.x + x1.y * y1.y + x1.z * y1.z + x1.w * y1.w;
#pragma unroll
        for (int m = 16; m >= 1; m >>= 1) s += __shfl_xor_sync(0xFFFFFFFF, s, m);
        if (lane == 0) g_qq[b * DIMN + d] = s + bq[d] + bref[d];
    }
}

__global__ void prep_split(const float* __restrict__ Wref) {
    int i = blockIdx.x * blockDim.x + threadIdx.x;  // 65536 total
    float w = Wref[i];
    __nv_bfloat16 h, l;
    split_bf16(w, h, l);
    g_Wh[i] = h;
    g_Wl[i] = l;
}

// ---------------- main kernel ----------------
// SMEM layout (dynamic, offsets from base):
//   A_hi: 4 k-chunks x (128 rows x 128B), SW128 per chunk   [0, 65536)
//   A_lo: same                                              [65536, 131072)
//   W stage p (p=0,1): base 131072 + p*32768; hi +0, lo +16384  (2 x 32KB)
//   v: 196608 (1KB)
#define SM_ALO 65536
#define SM_W   131072
#define SM_V   196608
#define SMEM_TOTAL 197632

__global__ void __launch_bounds__(256, 1) attn_main(const float* __restrict__ enc,
                                                    const float* __restrict__ vvec,
                                                    float* __restrict__ out) {
    extern __shared__ char smem[];
    const uint32_t sb = smem_u32(smem);
    const int tid = threadIdx.x;
    const int wid = tid >> 5;
    const int lane = tid & 31;
    const int k = blockIdx.x;
    const int b0 = blockIdx.y * 128;
    const int kb = k * BSZ + b0;       // global row base of this CTA's A tile
    const int m0 = wid * 16;           // warp's row base within the tile

    float* v_s = (float*)(smem + SM_V);
    v_s[tid] = vvec[tid];

    // per-lane ldmatrix base offsets (within a 16KB chunk / W stage)
    const uint32_t a_off0 = (uint32_t)((m0 + (lane & 15)) * 128 + (lane >> 4) * 16);
    const uint32_t w_row = (uint32_t)((lane & 7) + ((lane & 16) ? 8 : 0));
    const uint32_t w_off0 = w_row * 128 + ((lane >> 3) & 1) * 16;

    // W stage issue: stage s = pass*4 + c; rows pass*128 + [0,128), cols c*64 + [0,64)
    auto issue_W = [&](int s) {
        const int pass = s >> 2, c = s & 3;
        uint32_t wst = sb + SM_W + (uint32_t)(s & 1) * 32768;
        const __nv_bfloat16* srcH = g_Wh + (pass * 128) * DIMN + c * 64;
        const __nv_bfloat16* srcL = g_Wl + (pass * 128) * DIMN + c * 64;
#pragma unroll
        for (int j = 0; j < 4; j++) {
            int gi = j * 256 + tid;           // 1024 granules of 16B
            int d = gi >> 3, seg = gi & 7;
            cp_async16(wst + swz((uint32_t)(d * 128 + seg * 16)),
                       srcH + d * DIMN + seg * 8);
        }
#pragma unroll
        for (int j = 0; j < 4; j++) {
            int gi = j * 256 + tid;
            int d = gi >> 3, seg = gi & 7;
            cp_async16(wst + 16384 + swz((uint32_t)(d * 128 + seg * 16)),
                       srcL + d * DIMN + seg * 8);
        }
        asm volatile("cp.async.commit_group;" ::: "memory");
    };

    // accumulators: 16 n-tiles x 4 regs (one 128-col half at a time)
    float acc[16][4];
    float u0 = 0.0f, u1 = 0.0f;

    // epilogue rows / qq pointers
    const int r0g = b0 + m0 + (lane >> 2);
    const int r1g = r0g + 8;
    const float* q0p = g_qq + (size_t)r0g * DIMN;
    const float* q1p = g_qq + (size_t)r1g * DIMN;
    const int cbase = 2 * (lane & 3);

    // ---- prologue: W stage 0 in flight, A chunk 0 in regs ----
    issue_W(0);
    float4 st[8];
#pragma unroll
    for (int j = 0; j < 8; j++) {
        int gi = j * 256 + tid;
        int m = gi >> 4, f4 = gi & 15;
        st[j] = *(const float4*)(enc + (size_t)(kb + m) * DIMN + f4 * 4);
    }

#pragma unroll
    for (int t = 0; t < 16; t++)
#pragma unroll
        for (int j = 0; j < 4; j++) acc[t][j] = 0.0f;

    for (int pass = 0; pass < 2; pass++) {
        for (int c = 0; c < 4; c++) {
            const int s = pass * 4 + c;
            const uint32_t ahi = sb + (uint32_t)c * 16384;
            const uint32_t alo = sb + SM_ALO + (uint32_t)c * 16384;
            const uint32_t wbase = sb + SM_W + (uint32_t)(s & 1) * 32768;

            if (pass == 0) {
                // split + STS A chunk c (disjoint from chunk c-1 readers)
#pragma unroll
                for (int j = 0; j < 8; j++) {
                    int gi = j * 256 + tid;
                    int m = gi >> 4, f4 = gi & 15;
                    __nv_bfloat16 h0, h1, h2, h3, l0, l1, l2, l3;
                    split_bf16(st[j].x, h0, l0);
                    split_bf16(st[j].y, h1, l1);
                    split_bf16(st[j].z, h2, l2);
                    split_bf16(st[j].w, h3, l3);
                    uint32_t sw = swz((uint32_t)(m * 128 + f4 * 8));
                    char* abp = (char*)smem + (size_t)c * 16384;
                    *(uint2*)(abp + sw) = make_uint2(pack2(h0, h1), pack2(h2, h3));
                    *(uint2*)(abp + SM_ALO + sw) =
                        make_uint2(pack2(l0, l1), pack2(l2, l3));
                }
                // prefetch next A chunk into regs
                if (c < 3) {
#pragma unroll
                    for (int j = 0; j < 8; j++) {
                        int gi = j * 256 + tid;
                        int m = gi >> 4, f4 = gi & 15;
                        st[j] = *(const float4*)(enc + (size_t)(kb + m) * DIMN +
                                                 (c + 1) * 64 + f4 * 4);
                    }
                }
            }

            // W stage s arrived (issued one compute phase ago)
            asm volatile("cp.async.wait_group 0;" ::: "memory");
            __syncthreads();
            if (s < 7) issue_W(s + 1);

            // ---- compute: 4 k-steps x 8 n-tiles x 3 split terms ----
#pragma unroll
            for (int kk = 0; kk < 4; kk++) {
                uint32_t aH[4], aL[4];
                ldsm4(aH, ahi + swz(a_off0 + kk * 32));
                ldsm4(aL, alo + swz(a_off0 + kk * 32));
#pragma unroll
                for (int np = 0; np < 8; np++) {
                    uint32_t wh[4], wl[4];
                    ldsm4(wh, wbase + swz(w_off0 + np * 2048 + kk * 32));
                    mma_bf16(acc[2 * np],     aH, wh[0], wh[1]);
                    mma_bf16(acc[2 * np + 1], aH, wh[2], wh[3]);
                    mma_bf16(acc[2 * np],     aL, wh[0], wh[1]);
                    mma_bf16(acc[2 * np + 1], aL, wh[2], wh[3]);
                    ldsm4(wl, wbase + 16384 + swz(w_off0 + np * 2048 + kk * 32));
                    mma_bf16(acc[2 * np],     aH, wl[0], wl[1]);
                    mma_bf16(acc[2 * np + 1], aH, wl[2], wl[3]);
                }
            }
        }

        // ---- per-pass partial epilogue over this 128-col half ----
#pragma unroll
        for (int t = 0; t < 16; t++) {
            int cb = pass * 128 + t * 8 + cbase;
            float2 qa = *(const float2*)(q0p + cb);
            float2 qb = *(const float2*)(q1p + cb);
            float2 vv = *(const float2*)(v_s + cb);
            u0 = fmaf(vv.x, tanha(acc[t][0] + qa.x), u0);
            u0 = fmaf(vv.y, tanha(acc[t][1] + qa.y), u0);
            u1 = fmaf(vv.x, tanha(acc[t][2] + qb.x), u1);
            u1 = fmaf(vv.y, tanha(acc[t][3] + qb.y), u1);
            acc[t][0] = acc[t][1] = acc[t][2] = acc[t][3] = 0.0f;
        }
    }

    // reduce across the 4 lanes that share each row
    u0 += __shfl_xor_sync(0xFFFFFFFF, u0, 1);
    u0 += __shfl_xor_sync(0xFFFFFFFF, u0, 2);
    u1 += __shfl_xor_sync(0xFFFFFFFF, u1, 1);
    u1 += __shfl_xor_sync(0xFFFFFFFF, u1, 2);

    if ((lane & 3) == 0) {
        out[(size_t)r0g * KTOK + k] = 10.0f * tanhf(u0);
        out[(size_t)r1g * KTOK + k] = 10.0f * tanhf(u1);
    }
}

// ---------------- launch ----------------
extern "C" void kernel_launch(void* const* d_in, const int* in_sizes, int n_in,
                              void* d_out, int out_size) {
    (void)in_sizes; (void)n_in; (void)out_size;
    const float* enc   = (const float*)d_in[0];
    const float* query = (const float*)d_in[1];
    const float* Wq    = (const float*)d_in[2];
    const float* bq    = (const float*)d_in[3];
    const float* Wref  = (const float*)d_in[4];
    const float* bref  = (const float*)d_in[5];
    const float* v     = (const float*)d_in[6];
    float* out = (float*)d_out;

    prep_qq<<<BSZ, DIMN>>>(query, Wq, bq, bref);
    prep_split<<<DIMN * DIMN / 256, 256>>>(Wref);

    cudaFuncSetAttribute(attn_main, cudaFuncAttributeMaxDynamicSharedMemorySize,
                         SMEM_TOTAL);
    dim3 grid(KTOK, 2);
    attn_main<<<grid, 256, SMEM_TOTAL>>>(enc, v, out);
}

// round 5
// speedup vs baseline: 1.1300x; 1.0028x over previous
#include <cuda_runtime.h>
#include <cuda_bf16.h>
#include <cstdint>
#include <cstddef>

// Problem constants
#define DIMN 256
#define KTOK 2048
#define BSZ  256

// ---------------- device globals (scratch; no allocs allowed) ----------------
__device__ __align__(16) float          g_qq[BSZ * DIMN];   // query@Wq^T + bq + bref
__device__ __align__(16) __nv_bfloat16  g_Wh[DIMN * DIMN];  // Wref hi split
__device__ __align__(16) __nv_bfloat16  g_Wl[DIMN * DIMN];  // Wref lo split

// ---------------- helpers ----------------
__device__ __forceinline__ uint32_t smem_u32(const void* p) {
    return (uint32_t)__cvta_generic_to_shared(p);
}

__device__ __forceinline__ uint32_t swz(uint32_t o) {
    return o ^ ((o >> 3) & 0x70);
}

__device__ __forceinline__ uint32_t pack2(__nv_bfloat16 a, __nv_bfloat16 b) {
    __nv_bfloat162 t(a, b);
    return *reinterpret_cast<uint32_t*>(&t);
}

__device__ __forceinline__ void split_bf16(float a, __nv_bfloat16& h, __nv_bfloat16& l) {
    h = __float2bfloat16(a);
    l = __float2bfloat16(a - __bfloat162float(h));
}

__device__ __forceinline__ float tanha(float x) {
    float y;
    asm("tanh.approx.f32 %0, %1;" : "=f"(y) : "f"(x));
    return y;
}

__device__ __forceinline__ void ldsm4(uint32_t* r, uint32_t addr) {
    asm volatile("ldmatrix.sync.aligned.m8n8.x4.shared.b16 {%0,%1,%2,%3}, [%4];"
                 : "=r"(r[0]), "=r"(r[1]), "=r"(r[2]), "=r"(r[3])
                 : "r"(addr));
}

__device__ __forceinline__ void mma_bf16(float* c, const uint32_t* a,
                                         uint32_t b0, uint32_t b1) {
    asm volatile(
        "mma.sync.aligned.m16n8k16.row.col.f32.bf16.bf16.f32 "
        "{%0,%1,%2,%3}, {%4,%5,%6,%7}, {%8,%9}, {%0,%1,%2,%3};"
        : "+f"(c[0]), "+f"(c[1]), "+f"(c[2]), "+f"(c[3])
        : "r"(a[0]), "r"(a[1]), "r"(a[2]), "r"(a[3]), "r"(b0), "r"(b1));
}

__device__ __forceinline__ void cp_async16(uint32_t dst, const void* src) {
    asm volatile("cp.async.cg.shared.global [%0], [%1], 16;"
                 :: "r"(dst), "l"(src) : "memory");
}

// ---------------- prep kernels ----------------
// qq[b,d] = sum_e query[b,e]*Wq[d,e] + bq[d] + bref[d]
// 8 independent accumulator chains, 8 LDG in flight.
__global__ void prep_qq(const float* __restrict__ query, const float* __restrict__ Wq,
                        const float* __restrict__ bq, const float* __restrict__ bref) {
    __shared__ __align__(16) float qrow[DIMN];
    const int b = blockIdx.x;
    const int d = threadIdx.x;
    qrow[d] = query[b * DIMN + d];
    __syncthreads();
    const float4* q4 = (const float4*)qrow;
    const float4* w = (const float4*)(Wq + (size_t)d * DIMN);
    float s0 = 0.f, s1 = 0.f, s2 = 0.f, s3 = 0.f;
    float s4 = 0.f, s5 = 0.f, s6 = 0.f, s7 = 0.f;
#pragma unroll
    for (int e = 0; e < 64; e += 8) {
        float4 w0 = w[e],     w1 = w[e + 1], w2 = w[e + 2], w3 = w[e + 3];
        float4 w4 = w[e + 4], w5 = w[e + 5], w6 = w[e + 6], w7 = w[e + 7];
        float4 q0 = q4[e],     q1 = q4[e + 1], q2 = q4[e + 2], q3 = q4[e + 3];
        float4 q5 = q4[e + 5], q6 = q4[e + 6], q7 = q4[e + 7], q8 = q4[e + 4];
        s0 = fmaf(w0.x, q0.x, fmaf(w0.y, q0.y, fmaf(w0.z, q0.z, fmaf(w0.w, q0.w, s0))));
        s1 = fmaf(w1.x, q1.x, fmaf(w1.y, q1.y, fmaf(w1.z, q1.z, fmaf(w1.w, q1.w, s1))));
        s2 = fmaf(w2.x, q2.x, fmaf(w2.y, q2.y, fmaf(w2.z, q2.z, fmaf(w2.w, q2.w, s2))));
        s3 = fmaf(w3.x, q3.x, fmaf(w3.y, q3.y, fmaf(w3.z, q3.z, fmaf(w3.w, q3.w, s3))));
        s4 = fmaf(w4.x, q8.x, fmaf(w4.y, q8.y, fmaf(w4.z, q8.z, fmaf(w4.w, q8.w, s4))));
        s5 = fmaf(w5.x, q5.x, fmaf(w5.y, q5.y, fmaf(w5.z, q5.z, fmaf(w5.w, q5.w, s5))));
        s6 = fmaf(w6.x, q6.x, fmaf(w6.y, q6.y, fmaf(w6.z, q6.z, fmaf(w6.w, q6.w, s6))));
        s7 = fmaf(w7.x, q7.x, fmaf(w7.y, q7.y, fmaf(w7.z, q7.z, fmaf(w7.w, q7.w, s7))));
    }
    g_qq[b * DIMN + d] = ((s0 + s1) + (s2 + s3)) + ((s4 + s5) + (s6 + s7))
                         + bq[d] + bref[d];
}

__global__ void prep_split(const float* __restrict__ Wref) {
    int i = blockIdx.x * blockDim.x + threadIdx.x;  // 65536 total
    float w = Wref[i];
    __nv_bfloat16 h, l;
    split_bf16(w, h, l);
    g_Wh[i] = h;
    g_Wl[i] = l;
}

// ---------------- main kernel ----------------
// SMEM layout (dynamic, offsets from base):
//   A_hi: 4 k-chunks x (128 rows x 128B), SW128 per chunk   [0, 65536)
//   A_lo: same                                              [65536, 131072)
//   W stage p (p=0,1): base 131072 + p*32768; hi +0, lo +16384  (2 x 32KB)
//   v: 196608 (1KB);  red reuses [0, 1024) after compute.
#define SM_ALO 65536
#define SM_W   131072
#define SM_V   196608
#define SMEM_TOTAL 197632

__global__ void __launch_bounds__(256, 1) attn_main(const float* __restrict__ enc,
                                                    const float* __restrict__ vvec,
                                                    float* __restrict__ out) {
    extern __shared__ char smem[];
    const uint32_t sb = smem_u32(smem);
    const int tid = threadIdx.x;
    const int wid = tid >> 5;
    const int lane = tid & 31;
    const int wm = wid & 3;            // M block: rows wm*32 .. +32
    const int wn = wid >> 2;           // N half within pass: cols wn*64 .. +64
    const int k = blockIdx.x;
    const int b0 = blockIdx.y * 128;
    const int kb = k * BSZ + b0;

    float* v_s = (float*)(smem + SM_V);
    v_s[tid] = vvec[tid];

    // per-lane SWIZZLED ldmatrix bases (bits 5-6 of raw base are 0 -> kk*32 via XOR)
    const uint32_t a0 = swz((uint32_t)((wm * 32 + (lane & 15)) * 128 + (lane >> 4) * 16));
    const uint32_t a1 = a0 + 2048;  // +16 rows (bits >= 11, additive)
    const uint32_t w_row = (uint32_t)((lane & 7) + ((lane & 16) ? 8 : 0));
    const uint32_t w0s = swz((uint32_t)((wn * 64 + w_row) * 128 + ((lane >> 3) & 1) * 16));

    // W stage issue: stage s = pass*4 + c; rows pass*128+[0,128), cols c*64+[0,64)
    auto issue_W = [&](int s) {
        const int pass = s >> 2, c = s & 3;
        uint32_t wst = sb + SM_W + (uint32_t)(s & 1) * 32768;
        const __nv_bfloat16* srcH = g_Wh + (pass * 128) * DIMN + c * 64;
        const __nv_bfloat16* srcL = g_Wl + (pass * 128) * DIMN + c * 64;
#pragma unroll
        for (int j = 0; j < 4; j++) {
            int gi = j * 256 + tid;
            int d = gi >> 3, seg = gi & 7;
            cp_async16(wst + swz((uint32_t)(d * 128 + seg * 16)),
                       srcH + d * DIMN + seg * 8);
        }
#pragma unroll
        for (int j = 0; j < 4; j++) {
            int gi = j * 256 + tid;
            int d = gi >> 3, seg = gi & 7;
            cp_async16(wst + 16384 + swz((uint32_t)(d * 128 + seg * 16)),
                       srcL + d * DIMN + seg * 8);
        }
        asm volatile("cp.async.commit_group;" ::: "memory");
    };

    // accumulators: 2 m-tiles x 8 n8-tiles x 4 regs
    float acc[2][8][4];
#pragma unroll
    for (int mt = 0; mt < 2; mt++)
#pragma unroll
        for (int t = 0; t < 8; t++)
#pragma unroll
            for (int j = 0; j < 4; j++) acc[mt][t][j] = 0.0f;

    float u00 = 0.f, u01 = 0.f, u10 = 0.f, u11 = 0.f;

    // epilogue row indices / qq pointers (rows wm*32 + q + {0,8,16,24})
    const int q = lane >> 2;
    const int rbase = b0 + wm * 32 + q;
    const float* qp0 = g_qq + (size_t)rbase * DIMN;
    const float* qp1 = g_qq + (size_t)(rbase + 8) * DIMN;
    const float* qp2 = g_qq + (size_t)(rbase + 16) * DIMN;
    const float* qp3 = g_qq + (size_t)(rbase + 24) * DIMN;
    const int cbase = 2 * (lane & 3);

    // ---- prologue: W stage 0 in flight, A chunk 0 in regs ----
    issue_W(0);
    float4 st[8];
#pragma unroll
    for (int j = 0; j < 8; j++) {
        int gi = j * 256 + tid;
        int m = gi >> 4, f4 = gi & 15;
        st[j] = *(const float4*)(enc + (size_t)(kb + m) * DIMN + f4 * 4);
    }

    for (int pass = 0; pass < 2; pass++) {
        for (int c = 0; c < 4; c++) {
            const int s = pass * 4 + c;
            const uint32_t ahi = sb + (uint32_t)c * 16384;
            const uint32_t alo = sb + SM_ALO + (uint32_t)c * 16384;
            const uint32_t wbase = sb + SM_W + (uint32_t)(s & 1) * 32768;

            if (pass == 0) {
                // split + STS A chunk c
#pragma unroll
                for (int j = 0; j < 8; j++) {
                    int gi = j * 256 + tid;
                    int m = gi >> 4, f4 = gi & 15;
                    __nv_bfloat16 h0, h1, h2, h3, l0, l1, l2, l3;
                    split_bf16(st[j].x, h0, l0);
                    split_bf16(st[j].y, h1, l1);
                    split_bf16(st[j].z, h2, l2);
                    split_bf16(st[j].w, h3, l3);
                    uint32_t sw = swz((uint32_t)(m * 128 + f4 * 8));
                    char* abp = (char*)smem + (size_t)c * 16384;
                    *(uint2*)(abp + sw) = make_uint2(pack2(h0, h1), pack2(h2, h3));
                    *(uint2*)(abp + SM_ALO + sw) =
                        make_uint2(pack2(l0, l1), pack2(l2, l3));
                }
                if (c < 3) {
#pragma unroll
                    for (int j = 0; j < 8; j++) {
                        int gi = j * 256 + tid;
                        int m = gi >> 4, f4 = gi & 15;
                        st[j] = *(const float4*)(enc + (size_t)(kb + m) * DIMN +
                                                 (c + 1) * 64 + f4 * 4);
                    }
                }
            }

            asm volatile("cp.async.wait_group 0;" ::: "memory");
            __syncthreads();
            if (s < 7) issue_W(s + 1);

            // ---- compute chunk: 4 kk x (2 m-tiles x 4 np x 3 terms) ----
#pragma unroll
            for (int kk = 0; kk < 4; kk++) {
                const uint32_t kx = (uint32_t)(kk * 32);
                uint32_t aH0[4], aH1[4], aL0[4], aL1[4];
                ldsm4(aH0, ahi + (a0 ^ kx));
                ldsm4(aH1, ahi + ((a1) ^ kx));
                ldsm4(aL0, alo + (a0 ^ kx));
                ldsm4(aL1, alo + ((a1) ^ kx));
                const uint32_t wk = w0s ^ kx;
                uint32_t wh[2][4], wl[2][4];
                ldsm4(wh[0], wbase + wk);
                ldsm4(wl[0], wbase + 16384 + wk);
#pragma unroll
                for (int np = 0; np < 4; np++) {
                    const int cur = np & 1, nxt = cur ^ 1;
                    if (np < 3) {
                        ldsm4(wh[nxt], wbase + wk + (np + 1) * 2048);
                        ldsm4(wl[nxt], wbase + 16384 + wk + (np + 1) * 2048);
                    }
                    float* c00 = acc[0][2 * np];
                    float* c01 = acc[0][2 * np + 1];
                    float* c10 = acc[1][2 * np];
                    float* c11 = acc[1][2 * np + 1];
                    mma_bf16(c00, aH0, wh[cur][0], wh[cur][1]);
                    mma_bf16(c01, aH0, wh[cur][2], wh[cur][3]);
                    mma_bf16(c10, aH1, wh[cur][0], wh[cur][1]);
                    mma_bf16(c11, aH1, wh[cur][2], wh[cur][3]);
                    mma_bf16(c00, aL0, wh[cur][0], wh[cur][1]);
                    mma_bf16(c01, aL0, wh[cur][2], wh[cur][3]);
                    mma_bf16(c10, aL1, wh[cur][0], wh[cur][1]);
                    mma_bf16(c11, aL1, wh[cur][2], wh[cur][3]);
                    mma_bf16(c00, aH0, wl[cur][0], wl[cur][1]);
                    mma_bf16(c01, aH0, wl[cur][2], wl[cur][3]);
                    mma_bf16(c10, aH1, wl[cur][0], wl[cur][1]);
                    mma_bf16(c11, aH1, wl[cur][2], wl[cur][3]);
                }
            }
        }

        // ---- per-pass partial epilogue over warp's 64-col slice ----
#pragma unroll
        for (int t = 0; t < 8; t++) {
            int cb = pass * 128 + wn * 64 + t * 8 + cbase;
            float2 vv = *(const float2*)(v_s + cb);
            float2 qa = *(const float2*)(qp0 + cb);
            float2 qb = *(const float2*)(qp1 + cb);
            float2 qc = *(const float2*)(qp2 + cb);
            float2 qd = *(const float2*)(qp3 + cb);
            u00 = fmaf(vv.x, tanha(acc[0][t][0] + qa.x), u00);
            u00 = fmaf(vv.y, tanha(acc[0][t][1] + qa.y), u00);
            u01 = fmaf(vv.x, tanha(acc[0][t][2] + qb.x), u01);
            u01 = fmaf(vv.y, tanha(acc[0][t][3] + qb.y), u01);
            u10 = fmaf(vv.x, tanha(acc[1][t][0] + qc.x), u10);
            u10 = fmaf(vv.y, tanha(acc[1][t][1] + qc.y), u10);
            u11 = fmaf(vv.x, tanha(acc[1][t][2] + qd.x), u11);
            u11 = fmaf(vv.y, tanha(acc[1][t][3] + qd.y), u11);
#pragma unroll
            for (int mt = 0; mt < 2; mt++)
#pragma unroll
                for (int j = 0; j < 4; j++) acc[mt][t][j] = 0.0f;
        }
    }

    // reduce across the 4 lanes sharing each row
    u00 += __shfl_xor_sync(0xFFFFFFFF, u00, 1);
    u00 += __shfl_xor_sync(0xFFFFFFFF, u00, 2);
    u01 += __shfl_xor_sync(0xFFFFFFFF, u01, 1);
    u01 += __shfl_xor_sync(0xFFFFFFFF, u01, 2);
    u10 += __shfl_xor_sync(0xFFFFFFFF, u10, 1);
    u10 += __shfl_xor_sync(0xFFFFFFFF, u10, 2);
    u11 += __shfl_xor_sync(0xFFFFFFFF, u11, 1);
    u11 += __shfl_xor_sync(0xFFFFFFFF, u11, 2);

    // cross-warp (wn) reduction via smem (reuse dead A region)
    __syncthreads();  // all compute done; A smem dead
    float* red = (float*)smem;  // [2][128]
    if ((lane & 3) == 0) {
        red[wn * 128 + wm * 32 + q] = u00;
        red[wn * 128 + wm * 32 + 8 + q] = u01;
        red[wn * 128 + wm * 32 + 16 + q] = u10;
        red[wn * 128 + wm * 32 + 24 + q] = u11;
    }
    __syncthreads();
    if (tid < 128) {
        float u = red[tid] + red[128 + tid];
        out[(size_t)(b0 + tid) * KTOK + k] = 10.0f * tanhf(u);
    }
}

// ---------------- launch ----------------
extern "C" void kernel_launch(void* const* d_in, const int* in_sizes, int n_in,
                              void* d_out, int out_size) {
    (void)in_sizes; (void)n_in; (void)out_size;
    const float* enc   = (const float*)d_in[0];
    const float* query = (const float*)d_in[1];
    const float* Wq    = (const float*)d_in[2];
    const float* bq    = (const float*)d_in[3];
    const float* Wref  = (const float*)d_in[4];
    const float* bref  = (const float*)d_in[5];
    const float* v     = (const float*)d_in[6];
    float* out = (float*)d_out;

    prep_qq<<<BSZ, DIMN>>>(query, Wq, bq, bref);
    prep_split<<<DIMN * DIMN / 256, 256>>>(Wref);

    cudaFuncSetAttribute(attn_main, cudaFuncAttributeMaxDynamicSharedMemorySize,
                         SMEM_TOTAL);
    dim3 grid(KTOK, 2);
    attn_main<<<grid, 256, SMEM_TOTAL>>>(enc, v, out);
}

// round 6
// speedup vs baseline: 1.1565x; 1.0235x over previous
#include <cuda_runtime.h>
#include <cuda_bf16.h>
#include <cstdint>
#include <cstddef>

// Problem constants
#define DIMN 256
#define KTOK 2048
#define BSZ  256

// ---------------- device globals (scratch; no allocs allowed) ----------------
__device__ __align__(16) float          g_qq[BSZ * DIMN];   // query@Wq^T + bq + bref
__device__ __align__(16) __nv_bfloat16  g_Wh[DIMN * DIMN];  // Wref hi split
__device__ __align__(16) __nv_bfloat16  g_Wl[DIMN * DIMN];  // Wref lo split

// ---------------- helpers ----------------
__device__ __forceinline__ uint32_t smem_u32(const void* p) {
    return (uint32_t)__cvta_generic_to_shared(p);
}

__device__ __forceinline__ uint32_t swz(uint32_t o) {
    return o ^ ((o >> 3) & 0x70);
}

__device__ __forceinline__ uint32_t pack2(__nv_bfloat16 a, __nv_bfloat16 b) {
    __nv_bfloat162 t(a, b);
    return *reinterpret_cast<uint32_t*>(&t);
}

__device__ __forceinline__ void split_bf16(float a, __nv_bfloat16& h, __nv_bfloat16& l) {
    h = __float2bfloat16(a);
    l = __float2bfloat16(a - __bfloat162float(h));
}

__device__ __forceinline__ float tanha(float x) {
    float y;
    asm("tanh.approx.f32 %0, %1;" : "=f"(y) : "f"(x));
    return y;
}

__device__ __forceinline__ void ldsm4(uint32_t* r, uint32_t addr) {
    asm volatile("ldmatrix.sync.aligned.m8n8.x4.shared.b16 {%0,%1,%2,%3}, [%4];"
                 : "=r"(r[0]), "=r"(r[1]), "=r"(r[2]), "=r"(r[3])
                 : "r"(addr));
}

__device__ __forceinline__ void mma_bf16(float* c, const uint32_t* a,
                                         uint32_t b0, uint32_t b1) {
    asm volatile(
        "mma.sync.aligned.m16n8k16.row.col.f32.bf16.bf16.f32 "
        "{%0,%1,%2,%3}, {%4,%5,%6,%7}, {%8,%9}, {%0,%1,%2,%3};"
        : "+f"(c[0]), "+f"(c[1]), "+f"(c[2]), "+f"(c[3])
        : "r"(a[0]), "r"(a[1]), "r"(a[2]), "r"(a[3]), "r"(b0), "r"(b1));
}

__device__ __forceinline__ void cp_async16(uint32_t dst, const void* src) {
    asm volatile("cp.async.cg.shared.global [%0], [%1], 16;"
                 :: "r"(dst), "l"(src) : "memory");
}

// ---------------- prep kernels ----------------
// qq[b,d] = sum_e query[b,e]*Wq[d,e] + bq[d] + bref[d]
// grid (256 b, 4 d-groups), block 256: tid = dr*4 + q; thread sums e in
// [q*64, q*64+64); 4 partials reduced through smem. 1024 CTAs, short chains.
__global__ void prep_qq(const float* __restrict__ query, const float* __restrict__ Wq,
                        const float* __restrict__ bq, const float* __restrict__ bref) {
    __shared__ __align__(16) float qrow[DIMN];
    __shared__ float red[256];
    const int b = blockIdx.x, g = blockIdx.y;
    const int tid = threadIdx.x;
    const int dr = tid >> 2, q = tid & 3;
    const int d = g * 64 + dr;
    qrow[tid] = query[b * DIMN + tid];
    __syncthreads();
    const float4* wrow = (const float4*)(Wq + (size_t)d * DIMN + q * 64);
    const float4* qq4 = (const float4*)(qrow + q * 64);
    float s0 = 0.f, s1 = 0.f, s2 = 0.f, s3 = 0.f;
#pragma unroll
    for (int j = 0; j < 16; j += 4) {
        float4 w0 = wrow[j], w1 = wrow[j + 1], w2 = wrow[j + 2], w3 = wrow[j + 3];
        float4 y0 = qq4[j], y1 = qq4[j + 1], y2 = qq4[j + 2], y3 = qq4[j + 3];
        s0 = fmaf(w0.x, y0.x, fmaf(w0.y, y0.y, fmaf(w0.z, y0.z, fmaf(w0.w, y0.w, s0))));
        s1 = fmaf(w1.x, y1.x, fmaf(w1.y, y1.y, fmaf(w1.z, y1.z, fmaf(w1.w, y1.w, s1))));
        s2 = fmaf(w2.x, y2.x, fmaf(w2.y, y2.y, fmaf(w2.z, y2.z, fmaf(w2.w, y2.w, s2))));
        s3 = fmaf(w3.x, y3.x, fmaf(w3.y, y3.y, fmaf(w3.z, y3.z, fmaf(w3.w, y3.w, s3))));
    }
    red[tid] = (s0 + s1) + (s2 + s3);
    __syncthreads();
    if (q == 0) {
        float s = (red[tid] + red[tid + 1]) + (red[tid + 2] + red[tid + 3]);
        g_qq[b * DIMN + d] = s + bq[d] + bref[d];
    }
}

__global__ void prep_split(const float* __restrict__ Wref) {
    int i = blockIdx.x * blockDim.x + threadIdx.x;  // 65536 total
    float w = Wref[i];
    __nv_bfloat16 h, l;
    split_bf16(w, h, l);
    g_Wh[i] = h;
    g_Wl[i] = l;
}

// ---------------- main kernel ----------------
// SMEM (97KB -> 2 CTAs/SM):
//   A (single buffer, one 64-k chunk): hi [0,16384), lo [16384,32768)
//   W stage p (p=0,1): 32768 + p*32768; hi +0, lo +16384
//   v: 98304 (1KB).  red reuses [0,1024) after final compute.
#define SM_ALO 16384
#define SM_W   32768
#define SM_V   98304
#define SMEM_TOTAL 99328

__global__ void __launch_bounds__(256, 2) attn_main(const float* __restrict__ enc,
                                                    const float* __restrict__ vvec,
                                                    float* __restrict__ out) {
    extern __shared__ char smem[];
    const uint32_t sb = smem_u32(smem);
    const int tid = threadIdx.x;
    const int wid = tid >> 5;
    const int lane = tid & 31;
    const int wm = wid & 3;            // M block: rows wm*32 .. +32
    const int wn = wid >> 2;           // N half within pass: cols wn*64 .. +64
    const int k = blockIdx.x;
    const int b0 = blockIdx.y * 128;
    const int kb = k * BSZ + b0;

    float* v_s = (float*)(smem + SM_V);
    v_s[tid] = vvec[tid];

    // per-lane swizzled ldmatrix bases
    const uint32_t a0 = swz((uint32_t)((wm * 32 + (lane & 15)) * 128 + (lane >> 4) * 16));
    const uint32_t a1 = a0 + 2048;  // +16 rows (additive above swizzle bits)
    const uint32_t w_row = (uint32_t)((lane & 7) + ((lane & 16) ? 8 : 0));
    const uint32_t w0s = swz((uint32_t)((wn * 64 + w_row) * 128 + ((lane >> 3) & 1) * 16));

    // W stage issue: stage s = pass*4 + c; d-rows pass*128+[0,128), k-cols c*64+[0,64)
    auto issue_W = [&](int s) {
        const int pass = s >> 2, c = s & 3;
        uint32_t wst = sb + SM_W + (uint32_t)(s & 1) * 32768;
        const __nv_bfloat16* srcH = g_Wh + (pass * 128) * DIMN + c * 64;
        const __nv_bfloat16* srcL = g_Wl + (pass * 128) * DIMN + c * 64;
#pragma unroll
        for (int j = 0; j < 4; j++) {
            int gi = j * 256 + tid;
            int d = gi >> 3, seg = gi & 7;
            cp_async16(wst + swz((uint32_t)(d * 128 + seg * 16)),
                       srcH + d * DIMN + seg * 8);
        }
#pragma unroll
        for (int j = 0; j < 4; j++) {
            int gi = j * 256 + tid;
            int d = gi >> 3, seg = gi & 7;
            cp_async16(wst + 16384 + swz((uint32_t)(d * 128 + seg * 16)),
                       srcL + d * DIMN + seg * 8);
        }
        asm volatile("cp.async.commit_group;" ::: "memory");
    };

    // accumulators: 2 m-tiles x 8 n8-tiles x 4 regs (one 128-col pass at a time)
    float acc[2][8][4];
#pragma unroll
    for (int mt = 0; mt < 2; mt++)
#pragma unroll
        for (int t = 0; t < 8; t++)
#pragma unroll
            for (int j = 0; j < 4; j++) acc[mt][t][j] = 0.0f;

    float u00 = 0.f, u01 = 0.f, u10 = 0.f, u11 = 0.f;

    // epilogue row indices / qq pointers (rows wm*32 + q + {0,8,16,24})
    const int q = lane >> 2;
    const int rbase = b0 + wm * 32 + q;
    const float* qp0 = g_qq + (size_t)rbase * DIMN;
    const float* qp1 = g_qq + (size_t)(rbase + 8) * DIMN;
    const float* qp2 = g_qq + (size_t)(rbase + 16) * DIMN;
    const float* qp3 = g_qq + (size_t)(rbase + 24) * DIMN;
    const int cbase = 2 * (lane & 3);

    issue_W(0);

    for (int s = 0; s < 8; s++) {
        const int c = s & 3;
        const uint32_t wbase = sb + SM_W + (uint32_t)(s & 1) * 32768;

        // previous compute done: A buf and W buf (s+1)&1 are free
        __syncthreads();

        // load A chunk c (both passes re-read; L2/HBM, overlapped across CTAs)
        float4 st[8];
#pragma unroll
        for (int j = 0; j < 8; j++) {
            int gi = j * 256 + tid;
            int m = gi >> 4, f4 = gi & 15;
            st[j] = *(const float4*)(enc + (size_t)(kb + m) * DIMN + c * 64 + f4 * 4);
        }
        if (s < 7) issue_W(s + 1);

        // split + STS A chunk
#pragma unroll
        for (int j = 0; j < 8; j++) {
            int gi = j * 256 + tid;
            int m = gi >> 4, f4 = gi & 15;
            __nv_bfloat16 h0, h1, h2, h3, l0, l1, l2, l3;
            split_bf16(st[j].x, h0, l0);
            split_bf16(st[j].y, h1, l1);
            split_bf16(st[j].z, h2, l2);
            split_bf16(st[j].w, h3, l3);
            uint32_t sw = swz((uint32_t)(m * 128 + f4 * 8));
            *(uint2*)(smem + sw) = make_uint2(pack2(h0, h1), pack2(h2, h3));
            *(uint2*)(smem + SM_ALO + sw) = make_uint2(pack2(l0, l1), pack2(l2, l3));
        }

        // W(s) arrived; W(s+1) stays in flight
        if (s < 7) {
            asm volatile("cp.async.wait_group 1;" ::: "memory");
        } else {
            asm volatile("cp.async.wait_group 0;" ::: "memory");
        }
        __syncthreads();

        // ---- compute chunk: 4 kk x 4 np x 12 MMA ----
#pragma unroll
        for (int kk = 0; kk < 4; kk++) {
            const uint32_t kx = (uint32_t)(kk * 32);
            uint32_t aH0[4], aH1[4], aL0[4], aL1[4];
            ldsm4(aH0, sb + (a0 ^ kx));
            ldsm4(aH1, sb + (a1 ^ kx));
            ldsm4(aL0, sb + SM_ALO + (a0 ^ kx));
            ldsm4(aL1, sb + SM_ALO + (a1 ^ kx));
            const uint32_t wk = w0s ^ kx;
#pragma unroll
            for (int np = 0; np < 4; np++) {
                uint32_t wh[4], wl[4];
                ldsm4(wh, wbase + wk + np * 2048);
                ldsm4(wl, wbase + 16384 + wk + np * 2048);
                float* c00 = acc[0][2 * np];
                float* c01 = acc[0][2 * np + 1];
                float* c10 = acc[1][2 * np];
                float* c11 = acc[1][2 * np + 1];
                mma_bf16(c00, aH0, wh[0], wh[1]);
                mma_bf16(c01, aH0, wh[2], wh[3]);
                mma_bf16(c10, aH1, wh[0], wh[1]);
                mma_bf16(c11, aH1, wh[2], wh[3]);
                mma_bf16(c00, aL0, wh[0], wh[1]);
                mma_bf16(c01, aL0, wh[2], wh[3]);
                mma_bf16(c10, aL1, wh[0], wh[1]);
                mma_bf16(c11, aL1, wh[2], wh[3]);
                mma_bf16(c00, aH0, wl[0], wl[1]);
                mma_bf16(c01, aH0, wl[2], wl[3]);
                mma_bf16(c10, aH1, wl[0], wl[1]);
                mma_bf16(c11, aH1, wl[2], wl[3]);
            }
        }

        // ---- end of a pass: fold this 128-col half into u, reset acc ----
        if (c == 3) {
            const int pass = s >> 2;
#pragma unroll
            for (int t = 0; t < 8; t++) {
                int cb = pass * 128 + wn * 64 + t * 8 + cbase;
                float2 vv = *(const float2*)(v_s + cb);
                float2 qa = *(const float2*)(qp0 + cb);
                float2 qb = *(const float2*)(qp1 + cb);
                float2 qc = *(const float2*)(qp2 + cb);
                float2 qd = *(const float2*)(qp3 + cb);
                u00 = fmaf(vv.x, tanha(acc[0][t][0] + qa.x), u00);
                u00 = fmaf(vv.y, tanha(acc[0][t][1] + qa.y), u00);
                u01 = fmaf(vv.x, tanha(acc[0][t][2] + qb.x), u01);
                u01 = fmaf(vv.y, tanha(acc[0][t][3] + qb.y), u01);
                u10 = fmaf(vv.x, tanha(acc[1][t][0] + qc.x), u10);
                u10 = fmaf(vv.y, tanha(acc[1][t][1] + qc.y), u10);
                u11 = fmaf(vv.x, tanha(acc[1][t][2] + qd.x), u11);
                u11 = fmaf(vv.y, tanha(acc[1][t][3] + qd.y), u11);
#pragma unroll
                for (int mt = 0; mt < 2; mt++)
#pragma unroll
                    for (int j = 0; j < 4; j++) acc[mt][t][j] = 0.0f;
            }
        }
    }

    // reduce across the 4 lanes sharing each row
    u00 += __shfl_xor_sync(0xFFFFFFFF, u00, 1);
    u00 += __shfl_xor_sync(0xFFFFFFFF, u00, 2);
    u01 += __shfl_xor_sync(0xFFFFFFFF, u01, 1);
    u01 += __shfl_xor_sync(0xFFFFFFFF, u01, 2);
    u10 += __shfl_xor_sync(0xFFFFFFFF, u10, 1);
    u10 += __shfl_xor_sync(0xFFFFFFFF, u10, 2);
    u11 += __shfl_xor_sync(0xFFFFFFFF, u11, 1);
    u11 += __shfl_xor_sync(0xFFFFFFFF, u11, 2);

    // cross-warp (wn) reduction via smem (A buffer is dead now)
    __syncthreads();
    float* red = (float*)smem;  // [2][128]
    if ((lane & 3) == 0) {
        red[wn * 128 + wm * 32 + q] = u00;
        red[wn * 128 + wm * 32 + 8 + q] = u01;
        red[wn * 128 + wm * 32 + 16 + q] = u10;
        red[wn * 128 + wm * 32 + 24 + q] = u11;
    }
    __syncthreads();
    if (tid < 128) {
        float u = red[tid] + red[128 + tid];
        out[(size_t)(b0 + tid) * KTOK + k] = 10.0f * tanhf(u);
    }
}

// ---------------- launch ----------------
extern "C" void kernel_launch(void* const* d_in, const int* in_sizes, int n_in,
                              void* d_out, int out_size) {
    (void)in_sizes; (void)n_in; (void)out_size;
    const float* enc   = (const float*)d_in[0];
    const float* query = (const float*)d_in[1];
    const float* Wq    = (const float*)d_in[2];
    const float* bq    = (const float*)d_in[3];
    const float* Wref  = (const float*)d_in[4];
    const float* bref  = (const float*)d_in[5];
    const float* v     = (const float*)d_in[6];
    float* out = (float*)d_out;

    prep_qq<<<dim3(BSZ, 4), 256>>>(query, Wq, bq, bref);
    prep_split<<<DIMN * DIMN / 256, 256>>>(Wref);

    cudaFuncSetAttribute(attn_main, cudaFuncAttributeMaxDynamicSharedMemorySize,
                         SMEM_TOTAL);
    dim3 grid(KTOK, 2);
    attn_main<<<grid, 256, SMEM_TOTAL>>>(enc, v, out);
}

// round 7
// speedup vs baseline: 1.6284x; 1.4081x over previous
#include <cuda_runtime.h>
#include <cuda_fp16.h>
#include <cstdint>
#include <cstddef>

// Problem constants
#define DIMN 256
#define KTOK 2048
#define BSZ  256

// ---------------- device globals (scratch; no allocs allowed) ----------------
__device__ __align__(16) float   g_qq[BSZ * DIMN];   // query@Wq^T + bq + bref
__device__ __align__(16) __half  g_W16[DIMN * DIMN]; // Wref rounded to fp16

// ---------------- helpers ----------------
__device__ __forceinline__ uint32_t smem_u32(const void* p) {
    return (uint32_t)__cvta_generic_to_shared(p);
}

__device__ __forceinline__ uint32_t swz(uint32_t o) {
    return o ^ ((o >> 3) & 0x70);
}

__device__ __forceinline__ uint32_t pack2h(__half a, __half b) {
    __half2 t(a, b);  // a at low half
    return *reinterpret_cast<uint32_t*>(&t);
}

__device__ __forceinline__ void split_f16(float a, __half& h, __half& l) {
    h = __float2half(a);
    l = __float2half(a - __half2float(h));
}

__device__ __forceinline__ float tanha(float x) {
    float y;
    asm("tanh.approx.f32 %0, %1;" : "=f"(y) : "f"(x));
    return y;
}

__device__ __forceinline__ void ldsm4(uint32_t* r, uint32_t addr) {
    asm volatile("ldmatrix.sync.aligned.m8n8.x4.shared.b16 {%0,%1,%2,%3}, [%4];"
                 : "=r"(r[0]), "=r"(r[1]), "=r"(r[2]), "=r"(r[3])
                 : "r"(addr));
}

__device__ __forceinline__ void mma_f16(float* c, const uint32_t* a,
                                        uint32_t b0, uint32_t b1) {
    asm volatile(
        "mma.sync.aligned.m16n8k16.row.col.f32.f16.f16.f32 "
        "{%0,%1,%2,%3}, {%4,%5,%6,%7}, {%8,%9}, {%0,%1,%2,%3};"
        : "+f"(c[0]), "+f"(c[1]), "+f"(c[2]), "+f"(c[3])
        : "r"(a[0]), "r"(a[1]), "r"(a[2]), "r"(a[3]), "r"(b0), "r"(b1));
}

__device__ __forceinline__ void cp_async16(uint32_t dst, const void* src) {
    asm volatile("cp.async.cg.shared.global [%0], [%1], 16;"
                 :: "r"(dst), "l"(src) : "memory");
}

// ---------------- prep kernels ----------------
// qq[b,d] = sum_e query[b,e]*Wq[d,e] + bq[d] + bref[d]
// 8 independent accumulator chains, 8 LDG in flight (best measured variant).
__global__ void prep_qq(const float* __restrict__ query, const float* __restrict__ Wq,
                        const float* __restrict__ bq, const float* __restrict__ bref) {
    __shared__ __align__(16) float qrow[DIMN];
    const int b = blockIdx.x;
    const int d = threadIdx.x;
    qrow[d] = query[b * DIMN + d];
    __syncthreads();
    const float4* q4 = (const float4*)qrow;
    const float4* w = (const float4*)(Wq + (size_t)d * DIMN);
    float s0 = 0.f, s1 = 0.f, s2 = 0.f, s3 = 0.f;
    float s4 = 0.f, s5 = 0.f, s6 = 0.f, s7 = 0.f;
#pragma unroll
    for (int e = 0; e < 64; e += 8) {
        float4 w0 = w[e],     w1 = w[e + 1], w2 = w[e + 2], w3 = w[e + 3];
        float4 w4 = w[e + 4], w5 = w[e + 5], w6 = w[e + 6], w7 = w[e + 7];
        float4 q0 = q4[e],     q1 = q4[e + 1], q2 = q4[e + 2], q3 = q4[e + 3];
        float4 q5 = q4[e + 5], q6 = q4[e + 6], q7 = q4[e + 7], q8 = q4[e + 4];
        s0 = fmaf(w0.x, q0.x, fmaf(w0.y, q0.y, fmaf(w0.z, q0.z, fmaf(w0.w, q0.w, s0))));
        s1 = fmaf(w1.x, q1.x, fmaf(w1.y, q1.y, fmaf(w1.z, q1.z, fmaf(w1.w, q1.w, s1))));
        s2 = fmaf(w2.x, q2.x, fmaf(w2.y, q2.y, fmaf(w2.z, q2.z, fmaf(w2.w, q2.w, s2))));
        s3 = fmaf(w3.x, q3.x, fmaf(w3.y, q3.y, fmaf(w3.z, q3.z, fmaf(w3.w, q3.w, s3))));
        s4 = fmaf(w4.x, q8.x, fmaf(w4.y, q8.y, fmaf(w4.z, q8.z, fmaf(w4.w, q8.w, s4))));
        s5 = fmaf(w5.x, q5.x, fmaf(w5.y, q5.y, fmaf(w5.z, q5.z, fmaf(w5.w, q5.w, s5))));
        s6 = fmaf(w6.x, q6.x, fmaf(w6.y, q6.y, fmaf(w6.z, q6.z, fmaf(w6.w, q6.w, s6))));
        s7 = fmaf(w7.x, q7.x, fmaf(w7.y, q7.y, fmaf(w7.z, q7.z, fmaf(w7.w, q7.w, s7))));
    }
    g_qq[b * DIMN + d] = ((s0 + s1) + (s2 + s3)) + ((s4 + s5) + (s6 + s7))
                         + bq[d] + bref[d];
}

__global__ void prep_w16(const float* __restrict__ Wref) {
    int i = blockIdx.x * blockDim.x + threadIdx.x;  // 65536 total
    g_W16[i] = __float2half(Wref[i]);
}

// ---------------- main kernel ----------------
// SMEM (65KB -> 2 CTAs/SM):
//   A chunk (single buffer): hi [0,16384), lo [16384,32768)
//   W stage p (p=0,1): 32768 + p*16384  (128 d-rows x 128B, fp16)
//   v: 65536 (1KB).  red reuses [0,1024) after final compute.
#define SM_ALO 16384
#define SM_W   32768
#define SM_V   65536
#define SMEM_TOTAL 66560

__global__ void __launch_bounds__(256, 2) attn_main(const float* __restrict__ enc,
                                                    const float* __restrict__ vvec,
                                                    float* __restrict__ out) {
    extern __shared__ char smem[];
    const uint32_t sb = smem_u32(smem);
    const int tid = threadIdx.x;
    const int wid = tid >> 5;
    const int lane = tid & 31;
    const int wm = wid & 3;            // M block: rows wm*32 .. +32
    const int wn = wid >> 2;           // N half within pass: cols wn*64 .. +64
    const int k = blockIdx.x;
    const int b0 = blockIdx.y * 128;
    const int kb = k * BSZ + b0;

    float* v_s = (float*)(smem + SM_V);
    v_s[tid] = vvec[tid];

    // per-lane swizzled ldmatrix bases
    const uint32_t a0 = swz((uint32_t)((wm * 32 + (lane & 15)) * 128 + (lane >> 4) * 16));
    const uint32_t a1 = a0 + 2048;  // +16 rows (additive above swizzle bits)
    const uint32_t w_row = (uint32_t)((lane & 7) + ((lane & 16) ? 8 : 0));
    const uint32_t w0s = swz((uint32_t)((wn * 64 + w_row) * 128 + ((lane >> 3) & 1) * 16));

    // W stage issue: stage s = pass*4 + c; d-rows pass*128+[0,128), k-cols c*64+[0,64)
    auto issue_W = [&](int s) {
        const int pass = s >> 2, c = s & 3;
        uint32_t wst = sb + SM_W + (uint32_t)(s & 1) * 16384;
        const __half* src = g_W16 + (pass * 128) * DIMN + c * 64;
#pragma unroll
        for (int j = 0; j < 4; j++) {
            int gi = j * 256 + tid;           // 1024 granules of 16B
            int d = gi >> 3, seg = gi & 7;
            cp_async16(wst + swz((uint32_t)(d * 128 + seg * 16)),
                       src + d * DIMN + seg * 8);
        }
        asm volatile("cp.async.commit_group;" ::: "memory");
    };

    // accumulators: 2 m-tiles x 8 n8-tiles x 4 regs (one 128-col pass at a time)
    float acc[2][8][4];
#pragma unroll
    for (int mt = 0; mt < 2; mt++)
#pragma unroll
        for (int t = 0; t < 8; t++)
#pragma unroll
            for (int j = 0; j < 4; j++) acc[mt][t][j] = 0.0f;

    float u00 = 0.f, u01 = 0.f, u10 = 0.f, u11 = 0.f;

    // epilogue row indices / qq pointers (rows wm*32 + q + {0,8,16,24})
    const int q = lane >> 2;
    const int rbase = b0 + wm * 32 + q;
    const float* qp0 = g_qq + (size_t)rbase * DIMN;
    const float* qp1 = g_qq + (size_t)(rbase + 8) * DIMN;
    const float* qp2 = g_qq + (size_t)(rbase + 16) * DIMN;
    const float* qp3 = g_qq + (size_t)(rbase + 24) * DIMN;
    const int cbase = 2 * (lane & 3);

    issue_W(0);

    for (int s = 0; s < 8; s++) {
        const int c = s & 3;
        const uint32_t wbase = sb + SM_W + (uint32_t)(s & 1) * 16384;

        // previous compute done: A buf and the other W buf are free
        __syncthreads();

        // load A chunk c (both passes re-read; HBM/L2, overlapped across CTAs)
        float4 st[8];
#pragma unroll
        for (int j = 0; j < 8; j++) {
            int gi = j * 256 + tid;
            int m = gi >> 4, f4 = gi & 15;
            st[j] = *(const float4*)(enc + (size_t)(kb + m) * DIMN + c * 64 + f4 * 4);
        }
        if (s < 7) issue_W(s + 1);

        // split + STS A chunk (fp16 hi/lo)
#pragma unroll
        for (int j = 0; j < 8; j++) {
            int gi = j * 256 + tid;
            int m = gi >> 4, f4 = gi & 15;
            __half h0, h1, h2, h3, l0, l1, l2, l3;
            split_f16(st[j].x, h0, l0);
            split_f16(st[j].y, h1, l1);
            split_f16(st[j].z, h2, l2);
            split_f16(st[j].w, h3, l3);
            uint32_t sw = swz((uint32_t)(m * 128 + f4 * 8));
            *(uint2*)(smem + sw) = make_uint2(pack2h(h0, h1), pack2h(h2, h3));
            *(uint2*)(smem + SM_ALO + sw) = make_uint2(pack2h(l0, l1), pack2h(l2, l3));
        }

        // W(s) arrived; W(s+1) stays in flight
        if (s < 7) {
            asm volatile("cp.async.wait_group 1;" ::: "memory");
        } else {
            asm volatile("cp.async.wait_group 0;" ::: "memory");
        }
        __syncthreads();

        // ---- compute chunk: 4 kk x 4 np x 8 MMA ----
#pragma unroll
        for (int kk = 0; kk < 4; kk++) {
            const uint32_t kx = (uint32_t)(kk * 32);
            uint32_t aH0[4], aH1[4], aL0[4], aL1[4];
            ldsm4(aH0, sb + (a0 ^ kx));
            ldsm4(aH1, sb + (a1 ^ kx));
            ldsm4(aL0, sb + SM_ALO + (a0 ^ kx));
            ldsm4(aL1, sb + SM_ALO + (a1 ^ kx));
            const uint32_t wk = w0s ^ kx;
#pragma unroll
            for (int np = 0; np < 4; np++) {
                uint32_t w[4];
                ldsm4(w, wbase + wk + np * 2048);
                float* c00 = acc[0][2 * np];
                float* c01 = acc[0][2 * np + 1];
                float* c10 = acc[1][2 * np];
                float* c11 = acc[1][2 * np + 1];
                mma_f16(c00, aH0, w[0], w[1]);
                mma_f16(c01, aH0, w[2], w[3]);
                mma_f16(c10, aH1, w[0], w[1]);
                mma_f16(c11, aH1, w[2], w[3]);
                mma_f16(c00, aL0, w[0], w[1]);
                mma_f16(c01, aL0, w[2], w[3]);
                mma_f16(c10, aL1, w[0], w[1]);
                mma_f16(c11, aL1, w[2], w[3]);
            }
        }

        // ---- end of a pass: fold this 128-col half into u, reset acc ----
        if (c == 3) {
            const int pass = s >> 2;
#pragma unroll
            for (int t = 0; t < 8; t++) {
                int cb = pass * 128 + wn * 64 + t * 8 + cbase;
                float2 vv = *(const float2*)(v_s + cb);
                float2 qa = *(const float2*)(qp0 + cb);
                float2 qb = *(const float2*)(qp1 + cb);
                float2 qc = *(const float2*)(qp2 + cb);
                float2 qd = *(const float2*)(qp3 + cb);
                u00 = fmaf(vv.x, tanha(acc[0][t][0] + qa.x), u00);
                u00 = fmaf(vv.y, tanha(acc[0][t][1] + qa.y), u00);
                u01 = fmaf(vv.x, tanha(acc[0][t][2] + qb.x), u01);
                u01 = fmaf(vv.y, tanha(acc[0][t][3] + qb.y), u01);
                u10 = fmaf(vv.x, tanha(acc[1][t][0] + qc.x), u10);
                u10 = fmaf(vv.y, tanha(acc[1][t][1] + qc.y), u10);
                u11 = fmaf(vv.x, tanha(acc[1][t][2] + qd.x), u11);
                u11 = fmaf(vv.y, tanha(acc[1][t][3] + qd.y), u11);
#pragma unroll
                for (int mt = 0; mt < 2; mt++)
#pragma unroll
                    for (int j = 0; j < 4; j++) acc[mt][t][j] = 0.0f;
            }
        }
    }

    // reduce across the 4 lanes sharing each row
    u00 += __shfl_xor_sync(0xFFFFFFFF, u00, 1);
    u00 += __shfl_xor_sync(0xFFFFFFFF, u00, 2);
    u01 += __shfl_xor_sync(0xFFFFFFFF, u01, 1);
    u01 += __shfl_xor_sync(0xFFFFFFFF, u01, 2);
    u10 += __shfl_xor_sync(0xFFFFFFFF, u10, 1);
    u10 += __shfl_xor_sync(0xFFFFFFFF, u10, 2);
    u11 += __shfl_xor_sync(0xFFFFFFFF, u11, 1);
    u11 += __shfl_xor_sync(0xFFFFFFFF, u11, 2);

    // cross-warp (wn) reduction via smem (A buffer is dead now)
    __syncthreads();
    float* red = (float*)smem;  // [2][128]
    if ((lane & 3) == 0) {
        red[wn * 128 + wm * 32 + q] = u00;
        red[wn * 128 + wm * 32 + 8 + q] = u01;
        red[wn * 128 + wm * 32 + 16 + q] = u10;
        red[wn * 128 + wm * 32 + 24 + q] = u11;
    }
    __syncthreads();
    if (tid < 128) {
        float u = red[tid] + red[128 + tid];
        out[(size_t)(b0 + tid) * KTOK + k] = 10.0f * tanhf(u);
    }
}

// ---------------- launch ----------------
extern "C" void kernel_launch(void* const* d_in, const int* in_sizes, int n_in,
                              void* d_out, int out_size) {
    (void)in_sizes; (void)n_in; (void)out_size;
    const float* enc   = (const float*)d_in[0];
    const float* query = (const float*)d_in[1];
    const float* Wq    = (const float*)d_in[2];
    const float* bq    = (const float*)d_in[3];
    const float* Wref  = (const float*)d_in[4];
    const float* bref  = (const float*)d_in[5];
    const float* v     = (const float*)d_in[6];
    float* out = (float*)d_out;

    prep_qq<<<BSZ, DIMN>>>(query, Wq, bq, bref);
    prep_w16<<<DIMN * DIMN / 256, 256>>>(Wref);

    cudaFuncSetAttribute(attn_main, cudaFuncAttributeMaxDynamicSharedMemorySize,
                         SMEM_TOTAL);
    dim3 grid(KTOK, 2);
    attn_main<<<grid, 256, SMEM_TOTAL>>>(enc, v, out);
}

// round 8
// speedup vs baseline: 2.3422x; 1.4383x over previous
#include <cuda_runtime.h>
#include <cuda_fp16.h>
#include <cstdint>
#include <cstddef>

// Problem constants
#define DIMN 256
#define KTOK 2048
#define BSZ  256

// ---------------- device globals (scratch; no allocs allowed) ----------------
__device__ __align__(16) float   g_qq[BSZ * DIMN];   // query@Wq^T + bq + bref
__device__ __align__(16) __half  g_W16[DIMN * DIMN]; // Wref rounded to fp16

// ---------------- helpers ----------------
__device__ __forceinline__ uint32_t smem_u32(const void* p) {
    return (uint32_t)__cvta_generic_to_shared(p);
}

__device__ __forceinline__ uint32_t swz(uint32_t o) {
    return o ^ ((o >> 3) & 0x70);
}

__device__ __forceinline__ uint32_t pack2h(__half a, __half b) {
    __half2 t(a, b);  // a at low half
    return *reinterpret_cast<uint32_t*>(&t);
}

__device__ __forceinline__ float tanha(float x) {
    float y;
    asm("tanh.approx.f32 %0, %1;" : "=f"(y) : "f"(x));
    return y;
}

__device__ __forceinline__ void ldsm4(uint32_t* r, uint32_t addr) {
    asm volatile("ldmatrix.sync.aligned.m8n8.x4.shared.b16 {%0,%1,%2,%3}, [%4];"
                 : "=r"(r[0]), "=r"(r[1]), "=r"(r[2]), "=r"(r[3])
                 : "r"(addr));
}

__device__ __forceinline__ void mma_f16(float* c, const uint32_t* a,
                                        uint32_t b0, uint32_t b1) {
    asm volatile(
        "mma.sync.aligned.m16n8k16.row.col.f32.f16.f16.f32 "
        "{%0,%1,%2,%3}, {%4,%5,%6,%7}, {%8,%9}, {%0,%1,%2,%3};"
        : "+f"(c[0]), "+f"(c[1]), "+f"(c[2]), "+f"(c[3])
        : "r"(a[0]), "r"(a[1]), "r"(a[2]), "r"(a[3]), "r"(b0), "r"(b1));
}

__device__ __forceinline__ void cp_async16(uint32_t dst, const void* src) {
    asm volatile("cp.async.cg.shared.global [%0], [%1], 16;"
                 :: "r"(dst), "l"(src) : "memory");
}

// ---------------- prep kernels ----------------
// qq[b,d] = sum_e query[b,e]*Wq[d,e] + bq[d] + bref[d]
// grid (256 b, 2 d-halves), block 128; one d per thread, 8 FMA chains.
__global__ void prep_qq(const float* __restrict__ query, const float* __restrict__ Wq,
                        const float* __restrict__ bq, const float* __restrict__ bref) {
    __shared__ __align__(16) float qrow[DIMN];
    const int b = blockIdx.x;
    const int tid = threadIdx.x;
    const int d = blockIdx.y * 128 + tid;
    qrow[tid] = query[b * DIMN + tid];
    qrow[tid + 128] = query[b * DIMN + tid + 128];
    __syncthreads();
    const float4* q4 = (const float4*)qrow;
    const float4* w = (const float4*)(Wq + (size_t)d * DIMN);
    float s0 = 0.f, s1 = 0.f, s2 = 0.f, s3 = 0.f;
    float s4 = 0.f, s5 = 0.f, s6 = 0.f, s7 = 0.f;
#pragma unroll
    for (int e = 0; e < 64; e += 8) {
        float4 w0 = w[e],     w1 = w[e + 1], w2 = w[e + 2], w3 = w[e + 3];
        float4 w4 = w[e + 4], w5 = w[e + 5], w6 = w[e + 6], w7 = w[e + 7];
        float4 q0 = q4[e],     q1 = q4[e + 1], q2 = q4[e + 2], q3 = q4[e + 3];
        float4 q5 = q4[e + 5], q6 = q4[e + 6], q7 = q4[e + 7], q8 = q4[e + 4];
        s0 = fmaf(w0.x, q0.x, fmaf(w0.y, q0.y, fmaf(w0.z, q0.z, fmaf(w0.w, q0.w, s0))));
        s1 = fmaf(w1.x, q1.x, fmaf(w1.y, q1.y, fmaf(w1.z, q1.z, fmaf(w1.w, q1.w, s1))));
        s2 = fmaf(w2.x, q2.x, fmaf(w2.y, q2.y, fmaf(w2.z, q2.z, fmaf(w2.w, q2.w, s2))));
        s3 = fmaf(w3.x, q3.x, fmaf(w3.y, q3.y, fmaf(w3.z, q3.z, fmaf(w3.w, q3.w, s3))));
        s4 = fmaf(w4.x, q8.x, fmaf(w4.y, q8.y, fmaf(w4.z, q8.z, fmaf(w4.w, q8.w, s4))));
        s5 = fmaf(w5.x, q5.x, fmaf(w5.y, q5.y, fmaf(w5.z, q5.z, fmaf(w5.w, q5.w, s5))));
        s6 = fmaf(w6.x, q6.x, fmaf(w6.y, q6.y, fmaf(w6.z, q6.z, fmaf(w6.w, q6.w, s6))));
        s7 = fmaf(w7.x, q7.x, fmaf(w7.y, q7.y, fmaf(w7.z, q7.z, fmaf(w7.w, q7.w, s7))));
    }
    g_qq[b * DIMN + d] = ((s0 + s1) + (s2 + s3)) + ((s4 + s5) + (s6 + s7))
                         + bq[d] + bref[d];
}

__global__ void prep_w16(const float* __restrict__ Wref) {
    int i = blockIdx.x * blockDim.x + threadIdx.x;  // 65536 total
    g_W16[i] = __float2half(Wref[i]);
}

// ---------------- main kernel ----------------
// SMEM (97KB -> 2 CTAs/SM):
//   A chunks 0..3 (fp16, write-once, whole K resident): c*16384, [0, 65536)
//   W stage p (p=0,1): 65536 + p*16384  (128 d-rows x 128B, fp16)
//   v: 98304 (1KB).  red reuses [0,1024) after final compute.
#define SM_W   65536
#define SM_V   98304
#define SMEM_TOTAL 99328

__global__ void __launch_bounds__(256, 2) attn_main(const float* __restrict__ enc,
                                                    const float* __restrict__ vvec,
                                                    float* __restrict__ out) {
    extern __shared__ char smem[];
    const uint32_t sb = smem_u32(smem);
    const int tid = threadIdx.x;
    const int wid = tid >> 5;
    const int lane = tid & 31;
    const int wm = wid & 3;            // M block: rows wm*32 .. +32
    const int wn = wid >> 2;           // N half within pass: cols wn*64 .. +64
    const int k = blockIdx.x;
    const int b0 = blockIdx.y * 128;
    const int kb = k * BSZ + b0;

    float* v_s = (float*)(smem + SM_V);
    v_s[tid] = vvec[tid];

    // per-lane swizzled ldmatrix bases
    const uint32_t a0 = swz((uint32_t)((wm * 32 + (lane & 15)) * 128 + (lane >> 4) * 16));
    const uint32_t a1 = a0 + 2048;  // +16 rows (additive above swizzle bits)
    const uint32_t w_row = (uint32_t)((lane & 7) + ((lane & 16) ? 8 : 0));
    const uint32_t w0s = swz((uint32_t)((wn * 64 + w_row) * 128 + ((lane >> 3) & 1) * 16));

    // W stage issue: stage s = pass*4 + c; d-rows pass*128+[0,128), k-cols c*64+[0,64)
    auto issue_W = [&](int s) {
        const int pass = s >> 2, c = s & 3;
        uint32_t wst = sb + SM_W + (uint32_t)(s & 1) * 16384;
        const __half* src = g_W16 + (pass * 128) * DIMN + c * 64;
#pragma unroll
        for (int j = 0; j < 4; j++) {
            int gi = j * 256 + tid;           // 1024 granules of 16B
            int d = gi >> 3, seg = gi & 7;
            cp_async16(wst + swz((uint32_t)(d * 128 + seg * 16)),
                       src + d * DIMN + seg * 8);
        }
        asm volatile("cp.async.commit_group;" ::: "memory");
    };

    // accumulators: 2 m-tiles x 8 n8-tiles x 4 regs (one 128-col pass at a time)
    float acc[2][8][4];
#pragma unroll
    for (int mt = 0; mt < 2; mt++)
#pragma unroll
        for (int t = 0; t < 8; t++)
#pragma unroll
            for (int j = 0; j < 4; j++) acc[mt][t][j] = 0.0f;

    float u00 = 0.f, u01 = 0.f, u10 = 0.f, u11 = 0.f;

    // epilogue row indices / qq pointers (rows wm*32 + q + {0,8,16,24})
    const int q = lane >> 2;
    const int rbase = b0 + wm * 32 + q;
    const float* qp0 = g_qq + (size_t)rbase * DIMN;
    const float* qp1 = g_qq + (size_t)(rbase + 8) * DIMN;
    const float* qp2 = g_qq + (size_t)(rbase + 16) * DIMN;
    const float* qp3 = g_qq + (size_t)(rbase + 24) * DIMN;
    const int cbase = 2 * (lane & 3);

    issue_W(0);

    for (int s = 0; s < 8; s++) {
        const int c = s & 3;
        const uint32_t abase = sb + (uint32_t)c * 16384;
        const uint32_t wbase = sb + SM_W + (uint32_t)(s & 1) * 16384;

        if (s < 4) {
            // pass 0: load A chunk c from gmem, convert fp16, STS (write-once)
            float4 st[8];
#pragma unroll
            for (int j = 0; j < 8; j++) {
                int gi = j * 256 + tid;
                int m = gi >> 4, f4 = gi & 15;
                st[j] = *(const float4*)(enc + (size_t)(kb + m) * DIMN +
                                         c * 64 + f4 * 4);
            }
#pragma unroll
            for (int j = 0; j < 8; j++) {
                int gi = j * 256 + tid;
                int m = gi >> 4, f4 = gi & 15;
                __half h0 = __float2half(st[j].x), h1 = __float2half(st[j].y);
                __half h2 = __float2half(st[j].z), h3 = __float2half(st[j].w);
                uint32_t sw = swz((uint32_t)(m * 128 + f4 * 8));
                *(uint2*)(smem + (size_t)c * 16384 + sw) =
                    make_uint2(pack2h(h0, h1), pack2h(h2, h3));
            }
        }

        // W(s) is the only group in flight here
        asm volatile("cp.async.wait_group 0;" ::: "memory");
        __syncthreads();  // A STS visible; all warps done with compute(s-1)
        if (s < 7) issue_W(s + 1);  // safe: other W buffer free after sync

        // ---- compute chunk: 4 kk x 4 np x 4 MMA ----
#pragma unroll
        for (int kk = 0; kk < 4; kk++) {
            const uint32_t kx = (uint32_t)(kk * 32);
            uint32_t aF0[4], aF1[4];
            ldsm4(aF0, abase + (a0 ^ kx));
            ldsm4(aF1, abase + (a1 ^ kx));
            const uint32_t wk = w0s ^ kx;
#pragma unroll
            for (int np = 0; np < 4; np++) {
                uint32_t w[4];
                ldsm4(w, wbase + wk + np * 2048);
                mma_f16(acc[0][2 * np],     aF0, w[0], w[1]);
                mma_f16(acc[0][2 * np + 1], aF0, w[2], w[3]);
                mma_f16(acc[1][2 * np],     aF1, w[0], w[1]);
                mma_f16(acc[1][2 * np + 1], aF1, w[2], w[3]);
            }
        }

        // ---- end of a pass: fold this 128-col half into u, reset acc ----
        if (c == 3) {
            const int pass = s >> 2;
#pragma unroll
            for (int t = 0; t < 8; t++) {
                int cb = pass * 128 + wn * 64 + t * 8 + cbase;
                float2 vv = *(const float2*)(v_s + cb);
                float2 qa = *(const float2*)(qp0 + cb);
                float2 qb = *(const float2*)(qp1 + cb);
                float2 qc = *(const float2*)(qp2 + cb);
                float2 qd = *(const float2*)(qp3 + cb);
                u00 = fmaf(vv.x, tanha(acc[0][t][0] + qa.x), u00);
                u00 = fmaf(vv.y, tanha(acc[0][t][1] + qa.y), u00);
                u01 = fmaf(vv.x, tanha(acc[0][t][2] + qb.x), u01);
                u01 = fmaf(vv.y, tanha(acc[0][t][3] + qb.y), u01);
                u10 = fmaf(vv.x, tanha(acc[1][t][0] + qc.x), u10);
                u10 = fmaf(vv.y, tanha(acc[1][t][1] + qc.y), u10);
                u11 = fmaf(vv.x, tanha(acc[1][t][2] + qd.x), u11);
                u11 = fmaf(vv.y, tanha(acc[1][t][3] + qd.y), u11);
#pragma unroll
                for (int mt = 0; mt < 2; mt++)
#pragma unroll
                    for (int j = 0; j < 4; j++) acc[mt][t][j] = 0.0f;
            }
        }
    }

    // reduce across the 4 lanes sharing each row
    u00 += __shfl_xor_sync(0xFFFFFFFF, u00, 1);
    u00 += __shfl_xor_sync(0xFFFFFFFF, u00, 2);
    u01 += __shfl_xor_sync(0xFFFFFFFF, u01, 1);
    u01 += __shfl_xor_sync(0xFFFFFFFF, u01, 2);
    u10 += __shfl_xor_sync(0xFFFFFFFF, u10, 1);
    u10 += __shfl_xor_sync(0xFFFFFFFF, u10, 2);
    u11 += __shfl_xor_sync(0xFFFFFFFF, u11, 1);
    u11 += __shfl_xor_sync(0xFFFFFFFF, u11, 2);

    // cross-warp (wn) reduction via smem (A chunk 0 is dead now)
    __syncthreads();
    float* red = (float*)smem;  // [2][128]
    if ((lane & 3) == 0) {
        red[wn * 128 + wm * 32 + q] = u00;
        red[wn * 128 + wm * 32 + 8 + q] = u01;
        red[wn * 128 + wm * 32 + 16 + q] = u10;
        red[wn * 128 + wm * 32 + 24 + q] = u11;
    }
    __syncthreads();
    if (tid < 128) {
        float u = red[tid] + red[128 + tid];
        out[(size_t)(b0 + tid) * KTOK + k] = 10.0f * tanhf(u);
    }
}

// ---------------- launch ----------------
extern "C" void kernel_launch(void* const* d_in, const int* in_sizes, int n_in,
                              void* d_out, int out_size) {
    (void)in_sizes; (void)n_in; (void)out_size;
    const float* enc   = (const float*)d_in[0];
    const float* query = (const float*)d_in[1];
    const float* Wq    = (const float*)d_in[2];
    const float* bq    = (const float*)d_in[3];
    const float* Wref  = (const float*)d_in[4];
    const float* bref  = (const float*)d_in[5];
    const float* v     = (const float*)d_in[6];
    float* out = (float*)d_out;

    prep_qq<<<dim3(BSZ, 2), 128>>>(query, Wq, bq, bref);
    prep_w16<<<DIMN * DIMN / 256, 256>>>(Wref);

    cudaFuncSetAttribute(attn_main, cudaFuncAttributeMaxDynamicSharedMemorySize,
                         SMEM_TOTAL);
    dim3 grid(KTOK, 2);
    attn_main<<<grid, 256, SMEM_TOTAL>>>(enc, v, out);
}